// round 2
// baseline (speedup 1.0000x reference)
#include <cuda_runtime.h>

#define BATCH 2
#define NPTS  16384
#define DDIM  3
#define FDIM  128
#define KNBR  4
#define BN    (BATCH*NPTS)           // 32768 (b,n) groups
#define PTS_TOTAL (BATCH*NPTS*DDIM)  // 98304 floats

// ---------------- scratch (device globals: no allocations allowed) ----------
__device__ float g_feat[BN*FDIM];    // 16 MB
__device__ float g_pA[PTS_TOTAL];
__device__ float g_pB[PTS_TOTAL];

// ---------------- small copy kernels (ping-pong bookkeeping) ----------------
__global__ void copy_in_kernel(const float* __restrict__ src) {
    int i = blockIdx.x*blockDim.x + threadIdx.x;
    if (i < PTS_TOTAL/4) ((float4*)g_pA)[i] = ((const float4*)src)[i];
}
__global__ void copy_ping_kernel(int dir) {  // cur -> nxt
    const float* cur = dir ? g_pB : g_pA;
    float*       nxt = dir ? g_pA : g_pB;
    int i = blockIdx.x*blockDim.x + threadIdx.x;
    if (i < PTS_TOTAL/4) ((float4*)nxt)[i] = ((const float4*)cur)[i];
}
__global__ void copy_out_kernel(float* __restrict__ dst, int dir) {
    const float* cur = dir ? g_pB : g_pA;
    int i = blockIdx.x*blockDim.x + threadIdx.x;
    if (i < PTS_TOTAL/4) ((float4*)dst)[i] = ((const float4*)cur)[i];
}

// ---------------- feature net: feat = relu(pcl@Wf1+bf1)@Wf2+bf2 -------------
__global__ __launch_bounds__(256) void feat_kernel(
    const float* __restrict__ pcl, const float* __restrict__ Wf1,
    const float* __restrict__ bf1, const float* __restrict__ Wf2,
    const float* __restrict__ bf2)
{
    extern __shared__ float sm[];
    float* sW  = sm;                 // 128*128
    float* sh1 = sm + FDIM*FDIM;     // 8 warps * 128
    int tid = threadIdx.x, wid = tid >> 5, lane = tid & 31;

    for (int i = tid; i < FDIM*FDIM/4; i += blockDim.x)
        ((float4*)sW)[i] = ((const float4*)Wf2)[i];
    __syncthreads();

    float4 bf2v = *(const float4*)(bf2 + lane*4);
    float4 bf1v = *(const float4*)(bf1 + lane*4);
    float4 w0 = *(const float4*)(Wf1 + 0*FDIM + lane*4);
    float4 w1 = *(const float4*)(Wf1 + 1*FDIM + lane*4);
    float4 w2 = *(const float4*)(Wf1 + 2*FDIM + lane*4);
    float* myh = sh1 + wid*FDIM;

    int gw = blockIdx.x*(blockDim.x >> 5) + wid;
    int stride = gridDim.x*(blockDim.x >> 5);
    for (int r = gw; r < BN; r += stride) {
        float x0 = pcl[r*3+0], x1 = pcl[r*3+1], x2 = pcl[r*3+2];
        float4 h;
        h.x = fmaxf(fmaf(x0,w0.x, fmaf(x1,w1.x, fmaf(x2,w2.x, bf1v.x))), 0.f);
        h.y = fmaxf(fmaf(x0,w0.y, fmaf(x1,w1.y, fmaf(x2,w2.y, bf1v.y))), 0.f);
        h.z = fmaxf(fmaf(x0,w0.z, fmaf(x1,w1.z, fmaf(x2,w2.z, bf1v.z))), 0.f);
        h.w = fmaxf(fmaf(x0,w0.w, fmaf(x1,w1.w, fmaf(x2,w2.w, bf1v.w))), 0.f);
        __syncwarp();
        *(float4*)(myh + lane*4) = h;
        __syncwarp();
        float a0=bf2v.x, a1=bf2v.y, a2=bf2v.z, a3=bf2v.w;
        #pragma unroll 8
        for (int c = 0; c < 32; c++) {
            float4 h4 = *(float4*)(myh + c*4);
            const float* wr = sW + (c*4)*FDIM + lane*4;
            float4 q0 = *(const float4*)(wr);
            float4 q1 = *(const float4*)(wr + FDIM);
            float4 q2 = *(const float4*)(wr + 2*FDIM);
            float4 q3 = *(const float4*)(wr + 3*FDIM);
            a0 += h4.x*q0.x + h4.y*q1.x + h4.z*q2.x + h4.w*q3.x;
            a1 += h4.x*q0.y + h4.y*q1.y + h4.z*q2.y + h4.w*q3.y;
            a2 += h4.x*q0.z + h4.y*q1.z + h4.z*q2.z + h4.w*q3.z;
            a3 += h4.x*q0.w + h4.y*q1.w + h4.z*q2.w + h4.w*q3.w;
        }
        *(float4*)(g_feat + r*FDIM + lane*4) = make_float4(a0,a1,a2,a3);
    }
}

// ---------------- one Langevin step: score net + scatter-add ----------------
// One warp per (b,n) group, handling its K=4 neighbor rows jointly.
__global__ __launch_bounds__(512) void step_kernel(
    const float* __restrict__ pcl_noisy,
    const float* __restrict__ W0, const float* __restrict__ b0,
    const float* __restrict__ Wb, const float* __restrict__ bb,
    const float* __restrict__ Wo, const float* __restrict__ bo,
    float s, int dir)
{
    const float* cur = dir ? g_pB : g_pA;
    float*       nxt = dir ? g_pA : g_pB;

    extern __shared__ float sm[];
    float* sW0 = sm;                          // 131*128 = 16768
    float* sWb = sm + 131*FDIM;               // 2*128*128 = 32768
    float* shs = sWb + 2*FDIM*FDIM;           // 16 warps * 4 rows * 128 = 8192
    int tid = threadIdx.x, wid = tid >> 5, lane = tid & 31;

    for (int i = tid; i < (131*FDIM)/4; i += blockDim.x)
        ((float4*)sW0)[i] = ((const float4*)W0)[i];
    for (int i = tid; i < (2*FDIM*FDIM)/4; i += blockDim.x)
        ((float4*)sWb)[i] = ((const float4*)Wb)[i];
    __syncthreads();

    float4 b0v  = *(const float4*)(b0 + lane*4);
    float4 bb0v = *(const float4*)(bb + lane*4);
    float4 bb1v = *(const float4*)(bb + FDIM + lane*4);
    float wo[4][3];
    #pragma unroll
    for (int q = 0; q < 4; q++) {
        wo[q][0] = Wo[(lane*4+q)*3 + 0];
        wo[q][1] = Wo[(lane*4+q)*3 + 1];
        wo[q][2] = Wo[(lane*4+q)*3 + 2];
    }
    float bo0 = bo[0], bo1 = bo[1], bo2 = bo[2];
    float* myh = shs + wid*4*FDIM;

    int gw  = blockIdx.x*16 + wid;                // 148*16 = 2368 warps
    int gs  = gw*14;                              // 14 groups per warp
    int ge  = gs + 14; if (ge > BN) ge = BN;

    for (int g = gs; g < ge; ++g) {
        int b = g >> 14;            // NPTS = 2^14
        int n = g & (NPTS-1);
        const float* pn = pcl_noisy + g*3;
        float p0 = pn[0], p1 = pn[1], p2 = pn[2];

        int nbr[4]; float xr[4][3];
        #pragma unroll
        for (int k = 0; k < 4; k++) {
            int nb = n + k - 2;                       // offsets -2,-1,0,1
            nb = nb < 0 ? 0 : (nb > NPTS-1 ? NPTS-1 : nb);
            nbr[k] = nb;
            const float* pc = cur + (b*NPTS + nb)*3;
            xr[k][0] = pc[0] - p0; xr[k][1] = pc[1] - p1; xr[k][2] = pc[2] - p2;
        }

        // ---- layer 0: shared feat part computed once for all 4 rows ----
        float4 fv = *(const float4*)(g_feat + g*FDIM + lane*4);
        __syncwarp();
        *(float4*)(myh + lane*4) = fv;
        __syncwarp();
        float fa0 = b0v.x, fa1 = b0v.y, fa2 = b0v.z, fa3 = b0v.w;
        #pragma unroll 8
        for (int c = 0; c < 32; c++) {
            float4 h4 = *(float4*)(myh + c*4);
            const float* wr = sW0 + (3 + c*4)*FDIM + lane*4;
            float4 q0 = *(const float4*)(wr);
            float4 q1 = *(const float4*)(wr + FDIM);
            float4 q2 = *(const float4*)(wr + 2*FDIM);
            float4 q3 = *(const float4*)(wr + 3*FDIM);
            fa0 += h4.x*q0.x + h4.y*q1.x + h4.z*q2.x + h4.w*q3.x;
            fa1 += h4.x*q0.y + h4.y*q1.y + h4.z*q2.y + h4.w*q3.y;
            fa2 += h4.x*q0.z + h4.y*q1.z + h4.z*q2.z + h4.w*q3.z;
            fa3 += h4.x*q0.w + h4.y*q1.w + h4.z*q2.w + h4.w*q3.w;
        }
        float4 wx0 = *(const float4*)(sW0 + 0*FDIM + lane*4);
        float4 wx1 = *(const float4*)(sW0 + 1*FDIM + lane*4);
        float4 wx2 = *(const float4*)(sW0 + 2*FDIM + lane*4);

        float h[4][4];
        #pragma unroll
        for (int k = 0; k < 4; k++) {
            h[k][0] = fmaxf(fa0 + xr[k][0]*wx0.x + xr[k][1]*wx1.x + xr[k][2]*wx2.x, 0.f);
            h[k][1] = fmaxf(fa1 + xr[k][0]*wx0.y + xr[k][1]*wx1.y + xr[k][2]*wx2.y, 0.f);
            h[k][2] = fmaxf(fa2 + xr[k][0]*wx0.z + xr[k][1]*wx1.z + xr[k][2]*wx2.z, 0.f);
            h[k][3] = fmaxf(fa3 + xr[k][0]*wx0.w + xr[k][1]*wx1.w + xr[k][2]*wx2.w, 0.f);
        }
        __syncwarp();
        #pragma unroll
        for (int k = 0; k < 4; k++)
            *(float4*)(myh + k*FDIM + lane*4) = make_float4(h[k][0],h[k][1],h[k][2],h[k][3]);
        __syncwarp();

        // ---- 2 residual blocks: h += relu(h@Wb + bb) ----
        #pragma unroll
        for (int ib = 0; ib < 2; ib++) {
            const float* Wr = sWb + ib*FDIM*FDIM;
            float4 bbv = ib ? bb1v : bb0v;
            float acc[4][4];
            #pragma unroll
            for (int k = 0; k < 4; k++) {
                acc[k][0] = bbv.x; acc[k][1] = bbv.y; acc[k][2] = bbv.z; acc[k][3] = bbv.w;
            }
            #pragma unroll 4
            for (int c = 0; c < 32; c++) {
                const float* wr = Wr + (c*4)*FDIM + lane*4;
                float4 q0 = *(const float4*)(wr);
                float4 q1 = *(const float4*)(wr + FDIM);
                float4 q2 = *(const float4*)(wr + 2*FDIM);
                float4 q3 = *(const float4*)(wr + 3*FDIM);
                #pragma unroll
                for (int k = 0; k < 4; k++) {
                    float4 h4 = *(float4*)(myh + k*FDIM + c*4);
                    acc[k][0] += h4.x*q0.x + h4.y*q1.x + h4.z*q2.x + h4.w*q3.x;
                    acc[k][1] += h4.x*q0.y + h4.y*q1.y + h4.z*q2.y + h4.w*q3.y;
                    acc[k][2] += h4.x*q0.z + h4.y*q1.z + h4.z*q2.z + h4.w*q3.z;
                    acc[k][3] += h4.x*q0.w + h4.y*q1.w + h4.z*q2.w + h4.w*q3.w;
                }
            }
            #pragma unroll
            for (int k = 0; k < 4; k++) {
                h[k][0] += fmaxf(acc[k][0], 0.f);
                h[k][1] += fmaxf(acc[k][1], 0.f);
                h[k][2] += fmaxf(acc[k][2], 0.f);
                h[k][3] += fmaxf(acc[k][3], 0.f);
            }
            if (ib == 0) {
                __syncwarp();
                #pragma unroll
                for (int k = 0; k < 4; k++)
                    *(float4*)(myh + k*FDIM + lane*4) = make_float4(h[k][0],h[k][1],h[k][2],h[k][3]);
                __syncwarp();
            }
        }

        // ---- output proj (128->3) + warp reduce + scatter-add ----
        #pragma unroll
        for (int k = 0; k < 4; k++) {
            float g0v = h[k][0]*wo[0][0] + h[k][1]*wo[1][0] + h[k][2]*wo[2][0] + h[k][3]*wo[3][0];
            float g1v = h[k][0]*wo[0][1] + h[k][1]*wo[1][1] + h[k][2]*wo[2][1] + h[k][3]*wo[3][1];
            float g2v = h[k][0]*wo[0][2] + h[k][1]*wo[1][2] + h[k][2]*wo[2][2] + h[k][3]*wo[3][2];
            #pragma unroll
            for (int off = 16; off > 0; off >>= 1) {
                g0v += __shfl_xor_sync(0xffffffffu, g0v, off);
                g1v += __shfl_xor_sync(0xffffffffu, g1v, off);
                g2v += __shfl_xor_sync(0xffffffffu, g2v, off);
            }
            if (lane == 0) {
                float* dst = nxt + (b*NPTS + nbr[k])*3;
                atomicAdd(dst + 0, s*(g0v + bo0));
                atomicAdd(dst + 1, s*(g1v + bo1));
                atomicAdd(dst + 2, s*(g2v + bo2));
            }
        }
    }
}

// ---------------------------------------------------------------------------
extern "C" void kernel_launch(void* const* d_in, const int* in_sizes, int n_in,
                              void* d_out, int out_size)
{
    const float* pcl = (const float*)d_in[0];
    const float* Wf1 = (const float*)d_in[1];
    const float* bf1 = (const float*)d_in[2];
    const float* Wf2 = (const float*)d_in[3];
    const float* bf2 = (const float*)d_in[4];
    const float* W0  = (const float*)d_in[5];
    const float* b0  = (const float*)d_in[6];
    const float* Wb  = (const float*)d_in[7];
    const float* bb  = (const float*)d_in[8];
    const float* Wo  = (const float*)d_in[9];
    const float* bo  = (const float*)d_in[10];

    size_t feat_smem = (size_t)(FDIM*FDIM + 8*FDIM) * sizeof(float);          // 69632
    size_t step_smem = (size_t)(131*FDIM + 2*FDIM*FDIM + 16*4*FDIM) * sizeof(float); // 230912
    cudaFuncSetAttribute(feat_kernel, cudaFuncAttributeMaxDynamicSharedMemorySize, (int)feat_smem);
    cudaFuncSetAttribute(step_kernel, cudaFuncAttributeMaxDynamicSharedMemorySize, (int)step_smem);

    feat_kernel<<<128, 256, feat_smem>>>(pcl, Wf1, bf1, Wf2, bf2);
    copy_in_kernel<<<PTS_TOTAL/4/256, 256>>>(pcl);

    float s = 0.2f;
    for (int i = 0; i < 4; i++) {
        copy_ping_kernel<<<PTS_TOTAL/4/256, 256>>>(i & 1);
        step_kernel<<<148, 512, step_smem>>>(pcl, W0, b0, Wb, bb, Wo, bo, s, i & 1);
        s *= 0.95f;
    }
    // steps 0..3 toggle A->B->A->B->A: final result lives in g_pA (dir=0)
    copy_out_kernel<<<PTS_TOTAL/4/256, 256>>>((float*)d_out, 0);
}

// round 3
// speedup vs baseline: 1.0908x; 1.0908x over previous
#include <cuda_runtime.h>

#define BATCH 2
#define NPTS  16384
#define DDIM  3
#define FDIM  128
#define KNBR  4
#define BN    (BATCH*NPTS)           // 32768 (b,n) groups
#define PTS_TOTAL (BATCH*NPTS*DDIM)  // 98304 floats

typedef unsigned long long u64;

// ---------------- f32x2 packed-math helpers (SASS FFMA2 path) ---------------
__device__ __forceinline__ u64 splat2(float x) {
    u64 r; unsigned xi = __float_as_uint(x);
    asm("mov.b64 %0, {%1, %1};" : "=l"(r) : "r"(xi));
    return r;
}
__device__ __forceinline__ u64 pack2(float x, float y) {
    u64 r;
    asm("mov.b64 %0, {%1, %2};" : "=l"(r) : "r"(__float_as_uint(x)), "r"(__float_as_uint(y)));
    return r;
}
__device__ __forceinline__ u64 fma2(u64 a, u64 b, u64 c) {
    u64 d;
    asm("fma.rn.f32x2 %0, %1, %2, %3;" : "=l"(d) : "l"(a), "l"(b), "l"(c));
    return d;
}
__device__ __forceinline__ float2 unpack2(u64 v) {
    unsigned lo, hi;
    asm("mov.b64 {%0, %1}, %2;" : "=r"(lo), "=r"(hi) : "l"(v));
    return make_float2(__uint_as_float(lo), __uint_as_float(hi));
}

// ---------------- scratch (device globals: no allocations allowed) ----------
__device__ float g_feat[BN*FDIM];    // 16 MB
__device__ float g_pA[PTS_TOTAL];
__device__ float g_pB[PTS_TOTAL];

// ---------------- small copy kernels (ping-pong bookkeeping) ----------------
__global__ void copy_in_kernel(const float* __restrict__ src) {
    int i = blockIdx.x*blockDim.x + threadIdx.x;
    if (i < PTS_TOTAL/4) ((float4*)g_pA)[i] = ((const float4*)src)[i];
}
__global__ void copy_ping_kernel(int dir) {  // cur -> nxt
    const float* cur = dir ? g_pB : g_pA;
    float*       nxt = dir ? g_pA : g_pB;
    int i = blockIdx.x*blockDim.x + threadIdx.x;
    if (i < PTS_TOTAL/4) ((float4*)nxt)[i] = ((const float4*)cur)[i];
}
__global__ void copy_out_kernel(float* __restrict__ dst, int dir) {
    const float* cur = dir ? g_pB : g_pA;
    int i = blockIdx.x*blockDim.x + threadIdx.x;
    if (i < PTS_TOTAL/4) ((float4*)dst)[i] = ((const float4*)cur)[i];
}

// ---------------- feature net: feat = relu(pcl@Wf1+bf1)@Wf2+bf2 -------------
__global__ __launch_bounds__(256) void feat_kernel(
    const float* __restrict__ pcl, const float* __restrict__ Wf1,
    const float* __restrict__ bf1, const float* __restrict__ Wf2,
    const float* __restrict__ bf2)
{
    extern __shared__ float sm[];
    float* sW  = sm;                 // 128*128
    float* sh1 = sm + FDIM*FDIM;     // 8 warps * 128
    int tid = threadIdx.x, wid = tid >> 5, lane = tid & 31;

    for (int i = tid; i < FDIM*FDIM/4; i += blockDim.x)
        ((float4*)sW)[i] = ((const float4*)Wf2)[i];
    __syncthreads();

    float4 bf2v = *(const float4*)(bf2 + lane*4);
    float4 bf1v = *(const float4*)(bf1 + lane*4);
    float4 w0 = *(const float4*)(Wf1 + 0*FDIM + lane*4);
    float4 w1 = *(const float4*)(Wf1 + 1*FDIM + lane*4);
    float4 w2 = *(const float4*)(Wf1 + 2*FDIM + lane*4);
    float* myh = sh1 + wid*FDIM;

    int gw = blockIdx.x*(blockDim.x >> 5) + wid;
    int stride = gridDim.x*(blockDim.x >> 5);
    for (int r = gw; r < BN; r += stride) {
        float x0 = pcl[r*3+0], x1 = pcl[r*3+1], x2 = pcl[r*3+2];
        float4 h;
        h.x = fmaxf(fmaf(x0,w0.x, fmaf(x1,w1.x, fmaf(x2,w2.x, bf1v.x))), 0.f);
        h.y = fmaxf(fmaf(x0,w0.y, fmaf(x1,w1.y, fmaf(x2,w2.y, bf1v.y))), 0.f);
        h.z = fmaxf(fmaf(x0,w0.z, fmaf(x1,w1.z, fmaf(x2,w2.z, bf1v.z))), 0.f);
        h.w = fmaxf(fmaf(x0,w0.w, fmaf(x1,w1.w, fmaf(x2,w2.w, bf1v.w))), 0.f);
        __syncwarp();
        *(float4*)(myh + lane*4) = h;
        __syncwarp();
        u64 a01 = pack2(bf2v.x, bf2v.y);
        u64 a23 = pack2(bf2v.z, bf2v.w);
        #pragma unroll 8
        for (int c = 0; c < 32; c++) {
            float4 h4 = *(float4*)(myh + c*4);
            const float* wr = sW + (c*4)*FDIM + lane*4;
            ulonglong2 q0 = *(const ulonglong2*)(wr);
            ulonglong2 q1 = *(const ulonglong2*)(wr + FDIM);
            ulonglong2 q2 = *(const ulonglong2*)(wr + 2*FDIM);
            ulonglong2 q3 = *(const ulonglong2*)(wr + 3*FDIM);
            u64 s0 = splat2(h4.x), s1 = splat2(h4.y), s2 = splat2(h4.z), s3 = splat2(h4.w);
            a01 = fma2(s0, q0.x, a01); a23 = fma2(s0, q0.y, a23);
            a01 = fma2(s1, q1.x, a01); a23 = fma2(s1, q1.y, a23);
            a01 = fma2(s2, q2.x, a01); a23 = fma2(s2, q2.y, a23);
            a01 = fma2(s3, q3.x, a01); a23 = fma2(s3, q3.y, a23);
        }
        float2 r01 = unpack2(a01), r23 = unpack2(a23);
        *(float4*)(g_feat + r*FDIM + lane*4) = make_float4(r01.x, r01.y, r23.x, r23.y);
    }
}

// ---------------- one Langevin step: score net + scatter-add ----------------
// One warp per (b,n) group, handling its K=4 neighbor rows jointly.
// GEMMs run on packed f32x2 (FFMA2): each lane owns output dims lane*4..+3,
// held as two f32x2 accumulators per row.
__global__ __launch_bounds__(512) void step_kernel(
    const float* __restrict__ pcl_noisy,
    const float* __restrict__ W0, const float* __restrict__ b0,
    const float* __restrict__ Wb, const float* __restrict__ bb,
    const float* __restrict__ Wo, const float* __restrict__ bo,
    float s, int dir)
{
    const float* cur = dir ? g_pB : g_pA;
    float*       nxt = dir ? g_pA : g_pB;

    extern __shared__ float sm[];
    float* sW0 = sm;                          // 131*128 = 16768
    float* sWb = sm + 131*FDIM;               // 2*128*128 = 32768
    float* shs = sWb + 2*FDIM*FDIM;           // 16 warps * 4 rows * 128 = 8192
    int tid = threadIdx.x, wid = tid >> 5, lane = tid & 31;

    for (int i = tid; i < (131*FDIM)/4; i += blockDim.x)
        ((float4*)sW0)[i] = ((const float4*)W0)[i];
    for (int i = tid; i < (2*FDIM*FDIM)/4; i += blockDim.x)
        ((float4*)sWb)[i] = ((const float4*)Wb)[i];
    __syncthreads();

    float4 b0v  = *(const float4*)(b0 + lane*4);
    float4 bb0v = *(const float4*)(bb + lane*4);
    float4 bb1v = *(const float4*)(bb + FDIM + lane*4);
    u64 bb0p01 = pack2(bb0v.x, bb0v.y), bb0p23 = pack2(bb0v.z, bb0v.w);
    u64 bb1p01 = pack2(bb1v.x, bb1v.y), bb1p23 = pack2(bb1v.z, bb1v.w);
    u64 b0p01  = pack2(b0v.x,  b0v.y),  b0p23  = pack2(b0v.z,  b0v.w);
    float wo[4][3];
    #pragma unroll
    for (int q = 0; q < 4; q++) {
        wo[q][0] = Wo[(lane*4+q)*3 + 0];
        wo[q][1] = Wo[(lane*4+q)*3 + 1];
        wo[q][2] = Wo[(lane*4+q)*3 + 2];
    }
    float bo0 = bo[0], bo1 = bo[1], bo2 = bo[2];
    float* myh = shs + wid*4*FDIM;

    int gw  = blockIdx.x*16 + wid;                // 148*16 = 2368 warps
    int gs  = gw*14;                              // 14 groups per warp
    int ge  = gs + 14; if (ge > BN) ge = BN;

    for (int g = gs; g < ge; ++g) {
        int b = g >> 14;            // NPTS = 2^14
        int n = g & (NPTS-1);
        const float* pn = pcl_noisy + g*3;
        float p0 = pn[0], p1 = pn[1], p2 = pn[2];

        int nbr[4]; float xr[4][3];
        #pragma unroll
        for (int k = 0; k < 4; k++) {
            int nb = n + k - 2;                       // offsets -2,-1,0,1
            nb = nb < 0 ? 0 : (nb > NPTS-1 ? NPTS-1 : nb);
            nbr[k] = nb;
            const float* pc = cur + (b*NPTS + nb)*3;
            xr[k][0] = pc[0] - p0; xr[k][1] = pc[1] - p1; xr[k][2] = pc[2] - p2;
        }

        // ---- layer 0: shared feat part computed once for all 4 rows ----
        float4 fv = *(const float4*)(g_feat + g*FDIM + lane*4);
        __syncwarp();
        *(float4*)(myh + lane*4) = fv;
        __syncwarp();
        u64 fa01 = b0p01, fa23 = b0p23;
        #pragma unroll 8
        for (int c = 0; c < 32; c++) {
            float4 h4 = *(float4*)(myh + c*4);
            const float* wr = sW0 + (3 + c*4)*FDIM + lane*4;
            ulonglong2 q0 = *(const ulonglong2*)(wr);
            ulonglong2 q1 = *(const ulonglong2*)(wr + FDIM);
            ulonglong2 q2 = *(const ulonglong2*)(wr + 2*FDIM);
            ulonglong2 q3 = *(const ulonglong2*)(wr + 3*FDIM);
            u64 s0 = splat2(h4.x), s1 = splat2(h4.y), s2 = splat2(h4.z), s3 = splat2(h4.w);
            fa01 = fma2(s0, q0.x, fa01); fa23 = fma2(s0, q0.y, fa23);
            fa01 = fma2(s1, q1.x, fa01); fa23 = fma2(s1, q1.y, fa23);
            fa01 = fma2(s2, q2.x, fa01); fa23 = fma2(s2, q2.y, fa23);
            fa01 = fma2(s3, q3.x, fa01); fa23 = fma2(s3, q3.y, fa23);
        }
        float2 f01 = unpack2(fa01), f23 = unpack2(fa23);
        float fa0 = f01.x, fa1 = f01.y, fa2 = f23.x, fa3 = f23.y;

        float4 wx0 = *(const float4*)(sW0 + 0*FDIM + lane*4);
        float4 wx1 = *(const float4*)(sW0 + 1*FDIM + lane*4);
        float4 wx2 = *(const float4*)(sW0 + 2*FDIM + lane*4);

        float h[4][4];
        #pragma unroll
        for (int k = 0; k < 4; k++) {
            h[k][0] = fmaxf(fa0 + xr[k][0]*wx0.x + xr[k][1]*wx1.x + xr[k][2]*wx2.x, 0.f);
            h[k][1] = fmaxf(fa1 + xr[k][0]*wx0.y + xr[k][1]*wx1.y + xr[k][2]*wx2.y, 0.f);
            h[k][2] = fmaxf(fa2 + xr[k][0]*wx0.z + xr[k][1]*wx1.z + xr[k][2]*wx2.z, 0.f);
            h[k][3] = fmaxf(fa3 + xr[k][0]*wx0.w + xr[k][1]*wx1.w + xr[k][2]*wx2.w, 0.f);
        }
        __syncwarp();
        #pragma unroll
        for (int k = 0; k < 4; k++)
            *(float4*)(myh + k*FDIM + lane*4) = make_float4(h[k][0],h[k][1],h[k][2],h[k][3]);
        __syncwarp();

        // ---- 2 residual blocks: h += relu(h@Wb + bb), packed f32x2 ----
        #pragma unroll
        for (int ib = 0; ib < 2; ib++) {
            const float* Wr = sWb + ib*FDIM*FDIM;
            u64 acc01[4], acc23[4];
            #pragma unroll
            for (int k = 0; k < 4; k++) {
                acc01[k] = ib ? bb1p01 : bb0p01;
                acc23[k] = ib ? bb1p23 : bb0p23;
            }
            #pragma unroll 4
            for (int c = 0; c < 32; c++) {
                const float* wr = Wr + (c*4)*FDIM + lane*4;
                ulonglong2 q0 = *(const ulonglong2*)(wr);
                ulonglong2 q1 = *(const ulonglong2*)(wr + FDIM);
                ulonglong2 q2 = *(const ulonglong2*)(wr + 2*FDIM);
                ulonglong2 q3 = *(const ulonglong2*)(wr + 3*FDIM);
                #pragma unroll
                for (int k = 0; k < 4; k++) {
                    float4 h4 = *(float4*)(myh + k*FDIM + c*4);
                    u64 s0 = splat2(h4.x), s1 = splat2(h4.y), s2 = splat2(h4.z), s3 = splat2(h4.w);
                    acc01[k] = fma2(s0, q0.x, acc01[k]); acc23[k] = fma2(s0, q0.y, acc23[k]);
                    acc01[k] = fma2(s1, q1.x, acc01[k]); acc23[k] = fma2(s1, q1.y, acc23[k]);
                    acc01[k] = fma2(s2, q2.x, acc01[k]); acc23[k] = fma2(s2, q2.y, acc23[k]);
                    acc01[k] = fma2(s3, q3.x, acc01[k]); acc23[k] = fma2(s3, q3.y, acc23[k]);
                }
            }
            #pragma unroll
            for (int k = 0; k < 4; k++) {
                float2 a01 = unpack2(acc01[k]), a23 = unpack2(acc23[k]);
                h[k][0] += fmaxf(a01.x, 0.f);
                h[k][1] += fmaxf(a01.y, 0.f);
                h[k][2] += fmaxf(a23.x, 0.f);
                h[k][3] += fmaxf(a23.y, 0.f);
            }
            if (ib == 0) {
                __syncwarp();
                #pragma unroll
                for (int k = 0; k < 4; k++)
                    *(float4*)(myh + k*FDIM + lane*4) = make_float4(h[k][0],h[k][1],h[k][2],h[k][3]);
                __syncwarp();
            }
        }

        // ---- output proj (128->3) + warp reduce + scatter-add ----
        #pragma unroll
        for (int k = 0; k < 4; k++) {
            float g0v = h[k][0]*wo[0][0] + h[k][1]*wo[1][0] + h[k][2]*wo[2][0] + h[k][3]*wo[3][0];
            float g1v = h[k][0]*wo[0][1] + h[k][1]*wo[1][1] + h[k][2]*wo[2][1] + h[k][3]*wo[3][1];
            float g2v = h[k][0]*wo[0][2] + h[k][1]*wo[1][2] + h[k][2]*wo[2][2] + h[k][3]*wo[3][2];
            #pragma unroll
            for (int off = 16; off > 0; off >>= 1) {
                g0v += __shfl_xor_sync(0xffffffffu, g0v, off);
                g1v += __shfl_xor_sync(0xffffffffu, g1v, off);
                g2v += __shfl_xor_sync(0xffffffffu, g2v, off);
            }
            if (lane == 0) {
                float* dst = nxt + (b*NPTS + nbr[k])*3;
                atomicAdd(dst + 0, s*(g0v + bo0));
                atomicAdd(dst + 1, s*(g1v + bo1));
                atomicAdd(dst + 2, s*(g2v + bo2));
            }
        }
    }
}

// ---------------------------------------------------------------------------
extern "C" void kernel_launch(void* const* d_in, const int* in_sizes, int n_in,
                              void* d_out, int out_size)
{
    const float* pcl = (const float*)d_in[0];
    const float* Wf1 = (const float*)d_in[1];
    const float* bf1 = (const float*)d_in[2];
    const float* Wf2 = (const float*)d_in[3];
    const float* bf2 = (const float*)d_in[4];
    const float* W0  = (const float*)d_in[5];
    const float* b0  = (const float*)d_in[6];
    const float* Wb  = (const float*)d_in[7];
    const float* bb  = (const float*)d_in[8];
    const float* Wo  = (const float*)d_in[9];
    const float* bo  = (const float*)d_in[10];

    size_t feat_smem = (size_t)(FDIM*FDIM + 8*FDIM) * sizeof(float);          // 69632
    size_t step_smem = (size_t)(131*FDIM + 2*FDIM*FDIM + 16*4*FDIM) * sizeof(float); // 230912
    cudaFuncSetAttribute(feat_kernel, cudaFuncAttributeMaxDynamicSharedMemorySize, (int)feat_smem);
    cudaFuncSetAttribute(step_kernel, cudaFuncAttributeMaxDynamicSharedMemorySize, (int)step_smem);

    feat_kernel<<<128, 256, feat_smem>>>(pcl, Wf1, bf1, Wf2, bf2);
    copy_in_kernel<<<PTS_TOTAL/4/256, 256>>>(pcl);

    float s = 0.2f;
    for (int i = 0; i < 4; i++) {
        copy_ping_kernel<<<PTS_TOTAL/4/256, 256>>>(i & 1);
        step_kernel<<<148, 512, step_smem>>>(pcl, W0, b0, Wb, bb, Wo, bo, s, i & 1);
        s *= 0.95f;
    }
    // steps 0..3 toggle A->B->A->B->A: final result lives in g_pA (dir=0)
    copy_out_kernel<<<PTS_TOTAL/4/256, 256>>>((float*)d_out, 0);
}

// round 4
// speedup vs baseline: 1.5817x; 1.4500x over previous
#include <cuda_runtime.h>

#define BATCH 2
#define NPTS  16384
#define FDIM  128
#define BN    (BATCH*NPTS)           // 32768 groups
#define PTS_TOTAL (BATCH*NPTS*3)     // 98304 floats
#define NTILES 1024                  // 131072 rows / 128 rows per tile
#define STEP_GRID 148

typedef unsigned long long u64;

// ---------------- f32x2 packed-math helpers (SASS FFMA2 path) ---------------
__device__ __forceinline__ u64 splat2(float x) {
    u64 r; unsigned xi = __float_as_uint(x);
    asm("mov.b64 %0, {%1, %1};" : "=l"(r) : "r"(xi));
    return r;
}
__device__ __forceinline__ u64 fma2(u64 a, u64 b, u64 c) {
    u64 d;
    asm("fma.rn.f32x2 %0, %1, %2, %3;" : "=l"(d) : "l"(a), "l"(b), "l"(c));
    return d;
}
__device__ __forceinline__ float2 unpack2(u64 v) {
    unsigned lo, hi;
    asm("mov.b64 {%0, %1}, %2;" : "=r"(lo), "=r"(hi) : "l"(v));
    return make_float2(__uint_as_float(lo), __uint_as_float(hi));
}

// ---------------- scratch (device globals: no allocations allowed) ----------
__device__ float g_pre[BN*FDIM];     // precomputed feat@W0f + b0  (16 MB)
__device__ float g_M[FDIM*FDIM];     // Wf2 @ W0[3:131]
__device__ float g_cvec[FDIM];       // bf2 @ W0[3:131] + b0
__device__ float g_pA[PTS_TOTAL];
__device__ float g_pB[PTS_TOTAL];

// ---------------- small copy kernels ----------------------------------------
__global__ void copy_in_kernel(const float* __restrict__ src) {
    int i = blockIdx.x*blockDim.x + threadIdx.x;
    if (i < PTS_TOTAL/4) ((float4*)g_pA)[i] = ((const float4*)src)[i];
}
__global__ void copy_ping_kernel(int dir) {  // cur -> nxt
    const float* cur = dir ? g_pB : g_pA;
    float*       nxt = dir ? g_pA : g_pB;
    int i = blockIdx.x*blockDim.x + threadIdx.x;
    if (i < PTS_TOTAL/4) ((float4*)nxt)[i] = ((const float4*)cur)[i];
}
__global__ void copy_out_kernel(float* __restrict__ dst, int dir) {
    const float* cur = dir ? g_pB : g_pA;
    int i = blockIdx.x*blockDim.x + threadIdx.x;
    if (i < PTS_TOTAL/4) ((float4*)dst)[i] = ((const float4*)cur)[i];
}

// ---------------- fold Wf2 @ W0_feat (tiny, one-off) -------------------------
__global__ void mm_kernel(const float* __restrict__ Wf2, const float* __restrict__ W0,
                          const float* __restrict__ b0, const float* __restrict__ bf2) {
    int i = blockIdx.x, j = threadIdx.x;
    if (i < FDIM) {
        float a = 0.f;
        for (int c = 0; c < FDIM; c++) a = fmaf(Wf2[i*FDIM+c], W0[(3+c)*FDIM + j], a);
        g_M[i*FDIM+j] = a;
    } else {
        float a = b0[j];
        for (int c = 0; c < FDIM; c++) a = fmaf(bf2[c], W0[(3+c)*FDIM + j], a);
        g_cvec[j] = a;
    }
}

// ---------------- precompute: pre = relu(pcl@Wf1+bf1) @ M + cvec -------------
__global__ __launch_bounds__(256) void precomp_kernel(
    const float* __restrict__ pcl, const float* __restrict__ Wf1,
    const float* __restrict__ bf1)
{
    extern __shared__ float sm[];
    float* sW  = sm;                 // 128*128
    float* sh1 = sm + FDIM*FDIM;     // 8 warps * 128
    int tid = threadIdx.x, wid = tid >> 5, lane = tid & 31;

    for (int i = tid; i < FDIM*FDIM/4; i += blockDim.x)
        ((float4*)sW)[i] = ((const float4*)g_M)[i];
    __syncthreads();

    float4 cvv  = *(const float4*)(g_cvec + lane*4);
    float4 bf1v = *(const float4*)(bf1 + lane*4);
    float4 w0 = *(const float4*)(Wf1 + 0*FDIM + lane*4);
    float4 w1 = *(const float4*)(Wf1 + 1*FDIM + lane*4);
    float4 w2 = *(const float4*)(Wf1 + 2*FDIM + lane*4);
    float* myh = sh1 + wid*FDIM;

    int gw = blockIdx.x*(blockDim.x >> 5) + wid;
    int stride = gridDim.x*(blockDim.x >> 5);
    for (int r = gw; r < BN; r += stride) {
        float x0 = pcl[r*3+0], x1 = pcl[r*3+1], x2 = pcl[r*3+2];
        float4 h;
        h.x = fmaxf(fmaf(x0,w0.x, fmaf(x1,w1.x, fmaf(x2,w2.x, bf1v.x))), 0.f);
        h.y = fmaxf(fmaf(x0,w0.y, fmaf(x1,w1.y, fmaf(x2,w2.y, bf1v.y))), 0.f);
        h.z = fmaxf(fmaf(x0,w0.z, fmaf(x1,w1.z, fmaf(x2,w2.z, bf1v.z))), 0.f);
        h.w = fmaxf(fmaf(x0,w0.w, fmaf(x1,w1.w, fmaf(x2,w2.w, bf1v.w))), 0.f);
        __syncwarp();
        *(float4*)(myh + lane*4) = h;
        __syncwarp();
        u64 a01 = splat2(0.f), a23 = splat2(0.f);
        {
            unsigned lo0 = __float_as_uint(cvv.x), hi0 = __float_as_uint(cvv.y);
            asm("mov.b64 %0, {%1, %2};" : "=l"(a01) : "r"(lo0), "r"(hi0));
            unsigned lo1 = __float_as_uint(cvv.z), hi1 = __float_as_uint(cvv.w);
            asm("mov.b64 %0, {%1, %2};" : "=l"(a23) : "r"(lo1), "r"(hi1));
        }
        #pragma unroll 8
        for (int c = 0; c < 32; c++) {
            float4 h4 = *(float4*)(myh + c*4);
            const float* wr = sW + (c*4)*FDIM + lane*4;
            ulonglong2 q0 = *(const ulonglong2*)(wr);
            ulonglong2 q1 = *(const ulonglong2*)(wr + FDIM);
            ulonglong2 q2 = *(const ulonglong2*)(wr + 2*FDIM);
            ulonglong2 q3 = *(const ulonglong2*)(wr + 3*FDIM);
            u64 s0 = splat2(h4.x), s1 = splat2(h4.y), s2 = splat2(h4.z), s3 = splat2(h4.w);
            a01 = fma2(s0, q0.x, a01); a23 = fma2(s0, q0.y, a23);
            a01 = fma2(s1, q1.x, a01); a23 = fma2(s1, q1.y, a23);
            a01 = fma2(s2, q2.x, a01); a23 = fma2(s2, q2.y, a23);
            a01 = fma2(s3, q3.x, a01); a23 = fma2(s3, q3.y, a23);
        }
        float2 r01 = unpack2(a01), r23 = unpack2(a23);
        *(float4*)(g_pre + r*FDIM + lane*4) = make_float4(r01.x, r01.y, r23.x, r23.y);
    }
}

// ---------------- one Langevin step: GEMM-tiled score net --------------------
// Persistent CTAs (grid=148, 512 thr, 1 CTA/SM). Weights in smem once.
// Tile = 128 rows (32 groups x K=4). Thread owns 8 rows x 4 cols.
// h tile in smem, column-major with granule swizzle: column cc stores its
// 32 16B-granules at phys = (g + (cc>>2)) & 31  -> conflict-free loads+stores.
#define SWB_OFF 0
#define SWX_OFF (2*FDIM*FDIM)            // 32768
#define SH_OFF  (2*FDIM*FDIM + 3*FDIM)   // 33152
#define STEP_SMEM ((2*FDIM*FDIM + 3*FDIM + FDIM*FDIM) * 4)  // 198656 B

__global__ __launch_bounds__(512, 1) void step_kernel(
    const float* __restrict__ pcl_noisy,
    const float* __restrict__ Wb, const float* __restrict__ bb,
    const float* __restrict__ W0, const float* __restrict__ Wo,
    const float* __restrict__ bo, float s, int dir)
{
    const float* cur = dir ? g_pB : g_pA;
    float*       nxt = dir ? g_pA : g_pB;

    extern __shared__ float sm[];
    float* sWb = sm + SWB_OFF;
    float* sWx = sm + SWX_OFF;
    float* sH  = sm + SH_OFF;
    int tid = threadIdx.x, w = tid >> 5, l = tid & 31;

    for (int i = tid; i < (2*FDIM*FDIM)/4; i += 512)
        ((float4*)sWb)[i] = ((const float4*)Wb)[i];
    for (int i = tid; i < (3*FDIM)/4; i += 512)
        ((float4*)sWx)[i] = ((const float4*)W0)[i];   // W0 rows 0..2
    __syncthreads();

    // per-thread constants
    float4 wx0 = *(const float4*)(sWx + 0*FDIM + 4*l);
    float4 wx1 = *(const float4*)(sWx + 1*FDIM + 4*l);
    float4 wx2 = *(const float4*)(sWx + 2*FDIM + 4*l);
    float bbv[2][4];
    #pragma unroll
    for (int j = 0; j < 4; j++) { bbv[0][j] = bb[4*l+j]; bbv[1][j] = bb[FDIM+4*l+j]; }
    float wo_[4][3];
    #pragma unroll
    for (int j = 0; j < 4; j++) {
        wo_[j][0] = Wo[(4*l+j)*3+0]; wo_[j][1] = Wo[(4*l+j)*3+1]; wo_[j][2] = Wo[(4*l+j)*3+2];
    }
    float bo0 = bo[0], bo1 = bo[1], bo2 = bo[2];

    int pA = ((2*w + l) & 31) << 2;      // own-store/own-read granule, rows 0..3
    int pB = ((2*w + 1 + l) & 31) << 2;  // rows 4..7

    for (int tile = blockIdx.x; tile < NTILES; tile += STEP_GRID) {
        int gA = tile*32 + 2*w;

        // ---- layer 0: h0 = relu(pre[g] + xr @ Wx) for this thread's 8r x 4c
        float hv[8][4];
        #pragma unroll
        for (int gg = 0; gg < 2; gg++) {
            int g = gA + gg, b = g >> 14, n = g & (NPTS-1);
            const float* cen = pcl_noisy + 3*g;
            float p0 = cen[0], p1 = cen[1], p2 = cen[2];
            const float* pb = cur + 3*(b << 14);
            float4 pre = *(const float4*)(g_pre + g*FDIM + 4*l);
            #pragma unroll
            for (int k = 0; k < 4; k++) {
                int nb = n + k - 2; nb = nb < 0 ? 0 : (nb > NPTS-1 ? NPTS-1 : nb);
                const float* pc = pb + 3*nb;
                float x0 = pc[0]-p0, x1 = pc[1]-p1, x2 = pc[2]-p2;
                int r = 4*gg + k;
                hv[r][0] = fmaxf(fmaf(x0,wx0.x, fmaf(x1,wx1.x, fmaf(x2,wx2.x, pre.x))), 0.f);
                hv[r][1] = fmaxf(fmaf(x0,wx0.y, fmaf(x1,wx1.y, fmaf(x2,wx2.y, pre.y))), 0.f);
                hv[r][2] = fmaxf(fmaf(x0,wx0.z, fmaf(x1,wx1.z, fmaf(x2,wx2.z, pre.z))), 0.f);
                hv[r][3] = fmaxf(fmaf(x0,wx0.w, fmaf(x1,wx1.w, fmaf(x2,wx2.w, pre.w))), 0.f);
            }
        }
        __syncthreads();   // previous tile's sH reads complete
        #pragma unroll
        for (int j = 0; j < 4; j++) {
            float* colp = sH + (4*l + j)*FDIM;
            *(float4*)(colp + pA) = make_float4(hv[0][j], hv[1][j], hv[2][j], hv[3][j]);
            *(float4*)(colp + pB) = make_float4(hv[4][j], hv[5][j], hv[6][j], hv[7][j]);
        }
        __syncthreads();

        // ---- 2 residual blocks: h += relu(h @ Wb[ib] + bb[ib]) ----
        #pragma unroll
        for (int ib = 0; ib < 2; ib++) {
            const float* Wr = sWb + ib*FDIM*FDIM;
            u64 acc[4][4];
            #pragma unroll
            for (int j = 0; j < 4; j++) {
                u64 bp = splat2(bbv[ib][j]);
                acc[0][j] = bp; acc[1][j] = bp; acc[2][j] = bp; acc[3][j] = bp;
            }
            #pragma unroll 4
            for (int cc = 0; cc < FDIM; cc++) {
                const float* colp = sH + cc*FDIM;
                int sh = cc >> 2;
                ulonglong2 ha = *(const ulonglong2*)(colp + (((2*w + sh) & 31) << 2));
                ulonglong2 hb2 = *(const ulonglong2*)(colp + (((2*w + 1 + sh) & 31) << 2));
                float4 wv = *(const float4*)(Wr + cc*FDIM + 4*l);
                u64 s0 = splat2(wv.x), s1 = splat2(wv.y), s2 = splat2(wv.z), s3 = splat2(wv.w);
                acc[0][0]=fma2(ha.x,s0,acc[0][0]); acc[1][0]=fma2(ha.y,s0,acc[1][0]);
                acc[2][0]=fma2(hb2.x,s0,acc[2][0]); acc[3][0]=fma2(hb2.y,s0,acc[3][0]);
                acc[0][1]=fma2(ha.x,s1,acc[0][1]); acc[1][1]=fma2(ha.y,s1,acc[1][1]);
                acc[2][1]=fma2(hb2.x,s1,acc[2][1]); acc[3][1]=fma2(hb2.y,s1,acc[3][1]);
                acc[0][2]=fma2(ha.x,s2,acc[0][2]); acc[1][2]=fma2(ha.y,s2,acc[1][2]);
                acc[2][2]=fma2(hb2.x,s2,acc[2][2]); acc[3][2]=fma2(hb2.y,s2,acc[3][2]);
                acc[0][3]=fma2(ha.x,s3,acc[0][3]); acc[1][3]=fma2(ha.y,s3,acc[1][3]);
                acc[2][3]=fma2(hb2.x,s3,acc[2][3]); acc[3][3]=fma2(hb2.y,s3,acc[3][3]);
            }
            // epilogue: read own h from tile, hv = h + relu(acc)
            #pragma unroll
            for (int j = 0; j < 4; j++) {
                const float* colp = sH + (4*l + j)*FDIM;
                float4 a  = *(const float4*)(colp + pA);
                float4 b4 = *(const float4*)(colp + pB);
                float2 e0 = unpack2(acc[0][j]), e1 = unpack2(acc[1][j]);
                float2 e2 = unpack2(acc[2][j]), e3 = unpack2(acc[3][j]);
                hv[0][j] = a.x  + fmaxf(e0.x, 0.f); hv[1][j] = a.y  + fmaxf(e0.y, 0.f);
                hv[2][j] = a.z  + fmaxf(e1.x, 0.f); hv[3][j] = a.w  + fmaxf(e1.y, 0.f);
                hv[4][j] = b4.x + fmaxf(e2.x, 0.f); hv[5][j] = b4.y + fmaxf(e2.y, 0.f);
                hv[6][j] = b4.z + fmaxf(e3.x, 0.f); hv[7][j] = b4.w + fmaxf(e3.y, 0.f);
            }
            if (ib == 0) {
                __syncthreads();
                #pragma unroll
                for (int j = 0; j < 4; j++) {
                    float* colp = sH + (4*l + j)*FDIM;
                    *(float4*)(colp + pA) = make_float4(hv[0][j], hv[1][j], hv[2][j], hv[3][j]);
                    *(float4*)(colp + pB) = make_float4(hv[4][j], hv[5][j], hv[6][j], hv[7][j]);
                }
                __syncthreads();
            }
        }

        // ---- output proj (128->3): warp-reduce over cols, then scatter-add
        float ra0 = 0.f, ra1 = 0.f, ra2 = 0.f;
        #pragma unroll
        for (int r = 0; r < 8; r++) {
            float a0 = hv[r][0]*wo_[0][0] + hv[r][1]*wo_[1][0] + hv[r][2]*wo_[2][0] + hv[r][3]*wo_[3][0];
            float a1 = hv[r][0]*wo_[0][1] + hv[r][1]*wo_[1][1] + hv[r][2]*wo_[2][1] + hv[r][3]*wo_[3][1];
            float a2 = hv[r][0]*wo_[0][2] + hv[r][1]*wo_[1][2] + hv[r][2]*wo_[2][2] + hv[r][3]*wo_[3][2];
            #pragma unroll
            for (int off = 16; off > 0; off >>= 1) {
                a0 += __shfl_xor_sync(0xffffffffu, a0, off);
                a1 += __shfl_xor_sync(0xffffffffu, a1, off);
                a2 += __shfl_xor_sync(0xffffffffu, a2, off);
            }
            if (l == r) { ra0 = a0; ra1 = a1; ra2 = a2; }
        }
        if (l < 8) {
            int g = gA + (l >> 2);
            int b = g >> 14, n = g & (NPTS-1);
            int nb = n + (l & 3) - 2; nb = nb < 0 ? 0 : (nb > NPTS-1 ? NPTS-1 : nb);
            float* dst = nxt + 3*((b << 14) | nb);
            atomicAdd(dst + 0, s*(ra0 + bo0));
            atomicAdd(dst + 1, s*(ra1 + bo1));
            atomicAdd(dst + 2, s*(ra2 + bo2));
        }
    }
}

// ---------------------------------------------------------------------------
extern "C" void kernel_launch(void* const* d_in, const int* in_sizes, int n_in,
                              void* d_out, int out_size)
{
    const float* pcl = (const float*)d_in[0];
    const float* Wf1 = (const float*)d_in[1];
    const float* bf1 = (const float*)d_in[2];
    const float* Wf2 = (const float*)d_in[3];
    const float* bf2 = (const float*)d_in[4];
    const float* W0  = (const float*)d_in[5];
    const float* b0  = (const float*)d_in[6];
    const float* Wb  = (const float*)d_in[7];
    const float* bb  = (const float*)d_in[8];
    const float* Wo  = (const float*)d_in[9];
    const float* bo  = (const float*)d_in[10];

    size_t pre_smem = (size_t)(FDIM*FDIM + 8*FDIM) * sizeof(float);  // 69632
    cudaFuncSetAttribute(precomp_kernel, cudaFuncAttributeMaxDynamicSharedMemorySize, (int)pre_smem);
    cudaFuncSetAttribute(step_kernel, cudaFuncAttributeMaxDynamicSharedMemorySize, STEP_SMEM);

    mm_kernel<<<FDIM+1, FDIM>>>(Wf2, W0, b0, bf2);
    precomp_kernel<<<128, 256, pre_smem>>>(pcl, Wf1, bf1);
    copy_in_kernel<<<PTS_TOTAL/4/256, 256>>>(pcl);

    float s = 0.2f;
    for (int i = 0; i < 4; i++) {
        copy_ping_kernel<<<PTS_TOTAL/4/256, 256>>>(i & 1);
        step_kernel<<<STEP_GRID, 512, STEP_SMEM>>>(pcl, Wb, bb, W0, Wo, bo, s, i & 1);
        s *= 0.95f;
    }
    // steps 0..3 toggle A->B->A->B->A: final result lives in g_pA
    copy_out_kernel<<<PTS_TOTAL/4/256, 256>>>((float*)d_out, 0);
}

// round 6
// speedup vs baseline: 4.6324x; 2.9289x over previous
#include <cuda_runtime.h>
#include <cuda_bf16.h>

#define BATCH 2
#define NPTS  16384
#define FDIM  128
#define BN    (BATCH*NPTS)           // 32768 groups
#define PTS_TOTAL (BATCH*NPTS*3)     // 98304 floats
#define NTILES 1024                  // 131072 rows / 128
#define PIT   136                    // bf16 row pitch (272B: conflict-free ldmatrix)
typedef unsigned int u32;
typedef unsigned long long u64;

// ---------------- low-level helpers -----------------------------------------
__device__ __forceinline__ u32 smem_u32(const void* p){
    u32 a; asm("{ .reg .u64 t; cvta.to.shared.u64 t, %1; cvt.u32.u64 %0, t; }"
               : "=r"(a) : "l"(p));
    return a;
}
__device__ __forceinline__ void ldsm_x4(u32 a, u32& r0, u32& r1, u32& r2, u32& r3){
    asm volatile("ldmatrix.sync.aligned.m8n8.x4.shared.b16 {%0,%1,%2,%3}, [%4];"
                 : "=r"(r0),"=r"(r1),"=r"(r2),"=r"(r3) : "r"(a));
}
__device__ __forceinline__ void ldsm_x2(u32 a, u32& r0, u32& r1){
    asm volatile("ldmatrix.sync.aligned.m8n8.x2.shared.b16 {%0,%1}, [%2];"
                 : "=r"(r0),"=r"(r1) : "r"(a));
}
__device__ __forceinline__ void mma16816(float* c, u32 a0, u32 a1, u32 a2, u32 a3,
                                         u32 b0, u32 b1){
    asm volatile("mma.sync.aligned.m16n8k16.row.col.f32.bf16.bf16.f32 "
                 "{%0,%1,%2,%3}, {%4,%5,%6,%7}, {%8,%9}, {%0,%1,%2,%3};"
                 : "+f"(c[0]),"+f"(c[1]),"+f"(c[2]),"+f"(c[3])
                 : "r"(a0),"r"(a1),"r"(a2),"r"(a3),"r"(b0),"r"(b1));
}
// f32x2 helpers (precomp kernel)
__device__ __forceinline__ u64 splat2(float x){
    u64 r; asm("mov.b64 %0, {%1, %1};" : "=l"(r) : "r"(__float_as_uint(x))); return r;
}
__device__ __forceinline__ u64 fma2(u64 a, u64 b, u64 c){
    u64 d; asm("fma.rn.f32x2 %0, %1, %2, %3;" : "=l"(d) : "l"(a), "l"(b), "l"(c)); return d;
}
__device__ __forceinline__ float2 unpack2(u64 v){
    u32 lo, hi; asm("mov.b64 {%0, %1}, %2;" : "=r"(lo), "=r"(hi) : "l"(v));
    return make_float2(__uint_as_float(lo), __uint_as_float(hi));
}

// ---------------- scratch ----------------------------------------------------
__device__ float  g_pre[BN*FDIM];     // feat@W0f + b0 (precomputed, 16MB)
__device__ float  g_M[FDIM*FDIM];
__device__ float  g_cvec[FDIM];
__device__ float  g_pA[PTS_TOTAL];
__device__ float  g_pB[PTS_TOTAL];
__device__ __nv_bfloat16 g_BT[2*FDIM*PIT];   // WbT bf16, pitch 136

// ---------------- copies -----------------------------------------------------
__global__ void copy_in_kernel(const float* __restrict__ src){
    int i = blockIdx.x*blockDim.x + threadIdx.x;
    if (i < PTS_TOTAL/4){ float4 v = ((const float4*)src)[i]; ((float4*)g_pA)[i]=v; ((float4*)g_pB)[i]=v; }
}
__global__ void copy_ping_kernel(int dir){
    const float* cur = dir ? g_pB : g_pA;
    float*       nxt = dir ? g_pA : g_pB;
    int i = blockIdx.x*blockDim.x + threadIdx.x;
    if (i < PTS_TOTAL/4) ((float4*)nxt)[i] = ((const float4*)cur)[i];
}
__global__ void copy_out_kernel(float* __restrict__ dst){
    int i = blockIdx.x*blockDim.x + threadIdx.x;
    if (i < PTS_TOTAL/4) ((float4*)dst)[i] = ((const float4*)g_pA)[i];
}

// ---------------- fold Wf2 @ W0_feat -----------------------------------------
__global__ void mm_kernel(const float* __restrict__ Wf2, const float* __restrict__ W0,
                          const float* __restrict__ b0, const float* __restrict__ bf2){
    int i = blockIdx.x, j = threadIdx.x;
    if (i < FDIM){
        float a = 0.f;
        for (int c = 0; c < FDIM; c++) a = fmaf(Wf2[i*FDIM+c], W0[(3+c)*FDIM + j], a);
        g_M[i*FDIM+j] = a;
    } else {
        float a = b0[j];
        for (int c = 0; c < FDIM; c++) a = fmaf(bf2[c], W0[(3+c)*FDIM + j], a);
        g_cvec[j] = a;
    }
}

// ---------------- prep: WbT bf16 (BT[l][n][k] = Wb[l][k][n]) -----------------
__global__ void prep_b_kernel(const float* __restrict__ Wb){
    int lay = blockIdx.x >> 7, n = blockIdx.x & 127, k = threadIdx.x;
    g_BT[(lay*FDIM + n)*PIT + k] = __float2bfloat16(Wb[(lay*FDIM + k)*FDIM + n]);
}

// ---------------- precompute: pre = relu(pcl@Wf1+bf1) @ M + cvec -------------
__global__ __launch_bounds__(256) void precomp_kernel(
    const float* __restrict__ pcl, const float* __restrict__ Wf1,
    const float* __restrict__ bf1)
{
    extern __shared__ float sm[];
    float* sW  = sm;
    float* sh1 = sm + FDIM*FDIM;
    int tid = threadIdx.x, wid = tid >> 5, lane = tid & 31;

    for (int i = tid; i < FDIM*FDIM/4; i += blockDim.x)
        ((float4*)sW)[i] = ((const float4*)g_M)[i];
    __syncthreads();

    float4 cvv  = *(const float4*)(g_cvec + lane*4);
    float4 bf1v = *(const float4*)(bf1 + lane*4);
    float4 w0 = *(const float4*)(Wf1 + 0*FDIM + lane*4);
    float4 w1 = *(const float4*)(Wf1 + 1*FDIM + lane*4);
    float4 w2 = *(const float4*)(Wf1 + 2*FDIM + lane*4);
    float* myh = sh1 + wid*FDIM;

    int gw = blockIdx.x*(blockDim.x >> 5) + wid;
    int stride = gridDim.x*(blockDim.x >> 5);
    for (int r = gw; r < BN; r += stride){
        float x0 = pcl[r*3+0], x1 = pcl[r*3+1], x2 = pcl[r*3+2];
        float4 h;
        h.x = fmaxf(fmaf(x0,w0.x, fmaf(x1,w1.x, fmaf(x2,w2.x, bf1v.x))), 0.f);
        h.y = fmaxf(fmaf(x0,w0.y, fmaf(x1,w1.y, fmaf(x2,w2.y, bf1v.y))), 0.f);
        h.z = fmaxf(fmaf(x0,w0.z, fmaf(x1,w1.z, fmaf(x2,w2.z, bf1v.z))), 0.f);
        h.w = fmaxf(fmaf(x0,w0.w, fmaf(x1,w1.w, fmaf(x2,w2.w, bf1v.w))), 0.f);
        __syncwarp();
        *(float4*)(myh + lane*4) = h;
        __syncwarp();
        u64 a01, a23;
        asm("mov.b64 %0, {%1, %2};" : "=l"(a01) : "r"(__float_as_uint(cvv.x)), "r"(__float_as_uint(cvv.y)));
        asm("mov.b64 %0, {%1, %2};" : "=l"(a23) : "r"(__float_as_uint(cvv.z)), "r"(__float_as_uint(cvv.w)));
        #pragma unroll 8
        for (int c = 0; c < 32; c++){
            float4 h4 = *(float4*)(myh + c*4);
            const float* wr = sW + (c*4)*FDIM + lane*4;
            ulonglong2 q0 = *(const ulonglong2*)(wr);
            ulonglong2 q1 = *(const ulonglong2*)(wr + FDIM);
            ulonglong2 q2 = *(const ulonglong2*)(wr + 2*FDIM);
            ulonglong2 q3 = *(const ulonglong2*)(wr + 3*FDIM);
            u64 s0 = splat2(h4.x), s1 = splat2(h4.y), s2 = splat2(h4.z), s3 = splat2(h4.w);
            a01 = fma2(s0, q0.x, a01); a23 = fma2(s0, q0.y, a23);
            a01 = fma2(s1, q1.x, a01); a23 = fma2(s1, q1.y, a23);
            a01 = fma2(s2, q2.x, a01); a23 = fma2(s2, q2.y, a23);
            a01 = fma2(s3, q3.x, a01); a23 = fma2(s3, q3.y, a23);
        }
        float2 r01 = unpack2(a01), r23 = unpack2(a23);
        *(float4*)(g_pre + r*FDIM + lane*4) = make_float4(r01.x, r01.y, r23.x, r23.y);
    }
}

// ---------------- HMMA step kernel -------------------------------------------
// SMEM map (bytes):
#define SM_BT 0                       // 2 x 128 x 136 bf16 = 69632
#define SM_A0 69632                   // 128 x 136 bf16 = 34816
#define SM_A1 104448                  // 34816
#define SM_WX 139264                  // 3 x 128 f32
#define SM_WO 140800                  // Wo^T 3 x 128 f32
#define SM_BB 142336                  // 2 x 128 f32
#define STEP_SMEM 143360

__device__ __forceinline__ void gemm_128(u32 aBase, u32 bBase, float acc[8][4]){
    #pragma unroll
    for (int kk = 0; kk < 8; kk++){
        u32 a0,a1,a2,a3;
        ldsm_x4(aBase + kk*32, a0,a1,a2,a3);
        #pragma unroll
        for (int nt = 0; nt < 8; nt++){
            u32 b0,b1;
            ldsm_x2(bBase + nt*(8*PIT*2) + kk*32, b0,b1);
            mma16816(acc[nt], a0,a1,a2,a3, b0,b1);
        }
    }
}

__global__ __launch_bounds__(512, 1) void step_mma_kernel(
    const float* __restrict__ pcl_noisy, const float* __restrict__ W0,
    const float* __restrict__ Wo, const float* __restrict__ bo,
    const float* __restrict__ bb, float s, int dir)
{
    extern __shared__ char smem[];
    u32 sb = smem_u32(smem);
    int tid = threadIdx.x, w = tid >> 5, l = tid & 31;
    int wm = w & 7, wn = w >> 3;
    const float* cur = dir ? g_pB : g_pA;
    float*       nxt = dir ? g_pA : g_pB;

    for (int i = tid; i < 69632/16; i += 512)
        ((float4*)(smem+SM_BT))[i] = ((const float4*)g_BT)[i];
    for (int i = tid; i < 384; i += 512) ((float*)(smem+SM_WX))[i] = W0[i];
    if (tid < 128){
        float* wo = (float*)(smem+SM_WO);
        wo[tid] = Wo[tid*3]; wo[128+tid] = Wo[tid*3+1]; wo[256+tid] = Wo[tid*3+2];
    }
    if (tid < 256) ((float*)(smem+SM_BB))[tid] = bb[tid];

    const float* sWx = (const float*)(smem+SM_WX);
    const float* sWo = (const float*)(smem+SM_WO);
    const float* sBB = (const float*)(smem+SM_BB);
    float bo0 = bo[0], bo1 = bo[1], bo2 = bo[2];

    // per-warp ldmatrix base addresses
    u32 aAdr0 = sb + SM_A0 + (u32)(((16*wm + (l & 15))*PIT + 8*(l >> 4)) * 2);
    u32 aAdr1 = aAdr0 + (SM_A1 - SM_A0);
    u32 bAdr  = sb + SM_BT + (u32)((((wn << 6) + (l & 7))*PIT + 8*((l >> 3) & 1)) * 2);
    // epilogue coords
    int cb = (wn << 6) + 2*(l & 3);       // this lane's first col
    int r0 = (wm << 4) + (l >> 2);        // rows r0, r0+8 in 128-row tile

    for (int tile = blockIdx.x; tile < NTILES; tile += 148){
        __syncthreads();   // prior-iteration A1 reads done; also covers init on iter 0

        // ---- layer 0: warp w computes rows 8w..8w+7, lane covers cols 4l..4l+3
        {
            int g0 = (tile << 5) + 2*w;
            #pragma unroll
            for (int gg = 0; gg < 2; gg++){
                int g = g0 + gg;
                int b = g >> 14, n = g & (NPTS-1);
                const float* cen = pcl_noisy + 3*g;
                float p0 = cen[0], p1 = cen[1], p2 = cen[2];
                float4 pv = *(const float4*)(g_pre + (g << 7) + 4*l);
                float4 wa = *(const float4*)(sWx + 4*l);
                float4 wbv = *(const float4*)(sWx + 128 + 4*l);
                float4 wc = *(const float4*)(sWx + 256 + 4*l);
                #pragma unroll
                for (int k = 0; k < 4; k++){
                    int nb = n + k - 2; nb = nb < 0 ? 0 : (nb > NPTS-1 ? NPTS-1 : nb);
                    const float* pc = cur + 3*((b << 14) | nb);
                    float x0 = pc[0]-p0, x1 = pc[1]-p1, x2 = pc[2]-p2;
                    float y0 = fmaxf(pv.x + x0*wa.x + x1*wbv.x + x2*wc.x, 0.f);
                    float y1 = fmaxf(pv.y + x0*wa.y + x1*wbv.y + x2*wc.y, 0.f);
                    float y2 = fmaxf(pv.z + x0*wa.z + x1*wbv.z + x2*wc.z, 0.f);
                    float y3 = fmaxf(pv.w + x0*wa.w + x1*wbv.w + x2*wc.w, 0.f);
                    __nv_bfloat162 pa = __floats2bfloat162_rn(y0, y1);
                    __nv_bfloat162 pb2 = __floats2bfloat162_rn(y2, y3);
                    int row = 8*w + 4*gg + k;
                    *(uint2*)(smem + SM_A0 + (row*PIT + 4*l)*2) =
                        make_uint2(*(u32*)&pa, *(u32*)&pb2);
                }
            }
        }
        __syncthreads();

        // ---- GEMM 1: acc = A0 @ Wb0^T ----
        float acc[8][4];
        #pragma unroll
        for (int nt = 0; nt < 8; nt++){
            acc[nt][0]=0.f; acc[nt][1]=0.f; acc[nt][2]=0.f; acc[nt][3]=0.f;
        }
        gemm_128(aAdr0, bAdr, acc);

        // ---- epilogue 1: h1 = h0 + relu(acc + bb0) -> A1 (fragment layout)
        #pragma unroll
        for (int nt = 0; nt < 8; nt++){
            int c = cb + nt*8;
            float bbx = sBB[c], bby = sBB[c+1];
            int offA = (r0*PIT + c)*2, offB = ((r0+8)*PIT + c)*2;
            float2 h0a = __bfloat1622float2(*(__nv_bfloat162*)(smem + SM_A0 + offA));
            float2 h0b = __bfloat1622float2(*(__nv_bfloat162*)(smem + SM_A0 + offB));
            float v0 = h0a.x + fmaxf(acc[nt][0] + bbx, 0.f);
            float v1 = h0a.y + fmaxf(acc[nt][1] + bby, 0.f);
            float v2 = h0b.x + fmaxf(acc[nt][2] + bbx, 0.f);
            float v3 = h0b.y + fmaxf(acc[nt][3] + bby, 0.f);
            *(__nv_bfloat162*)(smem + SM_A1 + offA) = __floats2bfloat162_rn(v0, v1);
            *(__nv_bfloat162*)(smem + SM_A1 + offB) = __floats2bfloat162_rn(v2, v3);
        }
        __syncthreads();

        // ---- GEMM 2: acc = A1 @ Wb1^T ----
        #pragma unroll
        for (int nt = 0; nt < 8; nt++){
            acc[nt][0]=0.f; acc[nt][1]=0.f; acc[nt][2]=0.f; acc[nt][3]=0.f;
        }
        gemm_128(aAdr1, bAdr + 69632/2, acc);   // layer 1 at +34816 bytes

        // ---- epilogue 2: h2 = h1 + relu(acc + bb1), fused 128->3 projection
        float s0a=0.f,s1a=0.f,s2a=0.f, s0b=0.f,s1b=0.f,s2b=0.f;
        #pragma unroll
        for (int nt = 0; nt < 8; nt++){
            int c = cb + nt*8;
            float bbx = sBB[128+c], bby = sBB[128+c+1];
            int offA = (r0*PIT + c)*2, offB = ((r0+8)*PIT + c)*2;
            float2 h1a = __bfloat1622float2(*(__nv_bfloat162*)(smem + SM_A1 + offA));
            float2 h1b = __bfloat1622float2(*(__nv_bfloat162*)(smem + SM_A1 + offB));
            float v0 = h1a.x + fmaxf(acc[nt][0] + bbx, 0.f);
            float v1 = h1a.y + fmaxf(acc[nt][1] + bby, 0.f);
            float v2 = h1b.x + fmaxf(acc[nt][2] + bbx, 0.f);
            float v3 = h1b.y + fmaxf(acc[nt][3] + bby, 0.f);
            float w0x = sWo[c],     w0y = sWo[c+1];
            float w1x = sWo[128+c], w1y = sWo[128+c+1];
            float w2x = sWo[256+c], w2y = sWo[256+c+1];
            s0a += v0*w0x + v1*w0y;  s1a += v0*w1x + v1*w1y;  s2a += v0*w2x + v1*w2y;
            s0b += v2*w0x + v3*w0y;  s1b += v2*w1x + v3*w1y;  s2b += v2*w2x + v3*w2y;
        }
        // quad reduce (lanes sharing l>>2)
        #pragma unroll
        for (int off = 1; off <= 2; off <<= 1){
            s0a += __shfl_xor_sync(0xffffffffu, s0a, off);
            s1a += __shfl_xor_sync(0xffffffffu, s1a, off);
            s2a += __shfl_xor_sync(0xffffffffu, s2a, off);
            s0b += __shfl_xor_sync(0xffffffffu, s0b, off);
            s1b += __shfl_xor_sync(0xffffffffu, s1b, off);
            s2b += __shfl_xor_sync(0xffffffffu, s2b, off);
        }
        if ((l & 3) == 0){
            float bx = wn ? 0.f : bo0, by = wn ? 0.f : bo1, bz = wn ? 0.f : bo2;
            #pragma unroll
            for (int half = 0; half < 2; half++){
                int row = r0 + half*8;
                int g = (tile << 5) + (row >> 2);
                int b = g >> 14, n = g & (NPTS-1), k = row & 3;
                int nb = n + k - 2; nb = nb < 0 ? 0 : (nb > NPTS-1 ? NPTS-1 : nb);
                float* dst = nxt + 3*((b << 14) | nb);
                float u0 = half ? s0b : s0a, u1 = half ? s1b : s1a, u2 = half ? s2b : s2a;
                atomicAdd(dst + 0, s*(u0 + bx));
                atomicAdd(dst + 1, s*(u1 + by));
                atomicAdd(dst + 2, s*(u2 + bz));
            }
        }
    }
}

// ---------------------------------------------------------------------------
extern "C" void kernel_launch(void* const* d_in, const int* in_sizes, int n_in,
                              void* d_out, int out_size)
{
    const float* pcl = (const float*)d_in[0];
    const float* Wf1 = (const float*)d_in[1];
    const float* bf1 = (const float*)d_in[2];
    const float* Wf2 = (const float*)d_in[3];
    const float* bf2 = (const float*)d_in[4];
    const float* W0  = (const float*)d_in[5];
    const float* b0  = (const float*)d_in[6];
    const float* Wb  = (const float*)d_in[7];
    const float* bb  = (const float*)d_in[8];
    const float* Wo  = (const float*)d_in[9];
    const float* bo  = (const float*)d_in[10];

    size_t pre_smem = (size_t)(FDIM*FDIM + 8*FDIM) * sizeof(float);
    cudaFuncSetAttribute(precomp_kernel, cudaFuncAttributeMaxDynamicSharedMemorySize, (int)pre_smem);
    cudaFuncSetAttribute(step_mma_kernel, cudaFuncAttributeMaxDynamicSharedMemorySize, STEP_SMEM);

    mm_kernel<<<FDIM+1, FDIM>>>(Wf2, W0, b0, bf2);
    prep_b_kernel<<<256, 128>>>(Wb);
    precomp_kernel<<<148, 256, pre_smem>>>(pcl, Wf1, bf1);
    copy_in_kernel<<<PTS_TOTAL/4/256, 256>>>(pcl);

    float s = 0.2f;
    for (int i = 0; i < 4; i++){
        if (i) copy_ping_kernel<<<PTS_TOTAL/4/256, 256>>>(i & 1);
        step_mma_kernel<<<148, 512, STEP_SMEM>>>(pcl, W0, Wo, bo, bb, s, i & 1);
        s *= 0.95f;
    }
    // dir sequence 0,1,0,1 -> final result in g_pA
    copy_out_kernel<<<PTS_TOTAL/4/256, 256>>>((float*)d_out);
}

// round 9
// speedup vs baseline: 4.6442x; 1.0025x over previous
#include <cuda_runtime.h>
#include <cuda_bf16.h>

#define BATCH 2
#define NPTS  16384
#define FDIM  128
#define BN    (BATCH*NPTS)           // 32768 groups
#define PTS_TOTAL (BATCH*NPTS*3)     // 98304 floats
#define NTILES 1024                  // 131072 rows / 128
#define PIT   136                    // bf16 row pitch (272B: conflict-free ldmatrix)
typedef unsigned int u32;
typedef unsigned long long u64;

// ---------------- low-level helpers -----------------------------------------
__device__ __forceinline__ u32 smem_u32(const void* p){
    u32 a; asm("{ .reg .u64 t; cvta.to.shared.u64 t, %1; cvt.u32.u64 %0, t; }"
               : "=r"(a) : "l"(p));
    return a;
}
__device__ __forceinline__ void ldsm_x4(u32 a, u32& r0, u32& r1, u32& r2, u32& r3){
    asm volatile("ldmatrix.sync.aligned.m8n8.x4.shared.b16 {%0,%1,%2,%3}, [%4];"
                 : "=r"(r0),"=r"(r1),"=r"(r2),"=r"(r3) : "r"(a));
}
__device__ __forceinline__ void mma16816(float* c, u32 a0, u32 a1, u32 a2, u32 a3,
                                         u32 b0, u32 b1){
    asm volatile("mma.sync.aligned.m16n8k16.row.col.f32.bf16.bf16.f32 "
                 "{%0,%1,%2,%3}, {%4,%5,%6,%7}, {%8,%9}, {%0,%1,%2,%3};"
                 : "+f"(c[0]),"+f"(c[1]),"+f"(c[2]),"+f"(c[3])
                 : "r"(a0),"r"(a1),"r"(a2),"r"(a3),"r"(b0),"r"(b1));
}
// f32x2 helpers (precomp kernel)
__device__ __forceinline__ u64 splat2(float x){
    u64 r; asm("mov.b64 %0, {%1, %1};" : "=l"(r) : "r"(__float_as_uint(x))); return r;
}
__device__ __forceinline__ u64 fma2(u64 a, u64 b, u64 c){
    u64 d; asm("fma.rn.f32x2 %0, %1, %2, %3;" : "=l"(d) : "l"(a), "l"(b), "l"(c)); return d;
}
__device__ __forceinline__ float2 unpack2(u64 v){
    u32 lo, hi; asm("mov.b64 {%0, %1}, %2;" : "=r"(lo), "=r"(hi) : "l"(v));
    return make_float2(__uint_as_float(lo), __uint_as_float(hi));
}

// ---------------- scratch ----------------------------------------------------
__device__ float  g_pre[BN*FDIM];     // feat@W0f + b0 (precomputed, 16MB)
__device__ float  g_M[FDIM*FDIM];
__device__ float  g_cvec[FDIM];
__device__ float  g_pA[PTS_TOTAL];
__device__ float  g_pB[PTS_TOTAL];
__device__ __nv_bfloat16 g_BT[2*FDIM*PIT];   // WbT bf16, pitch 136

// ---------------- copies -----------------------------------------------------
__global__ void copy_in_kernel(const float* __restrict__ src){
    int i = blockIdx.x*blockDim.x + threadIdx.x;
    if (i < PTS_TOTAL/4){ float4 v = ((const float4*)src)[i]; ((float4*)g_pA)[i]=v; ((float4*)g_pB)[i]=v; }
}
__global__ void copy_ping_kernel(int dir){
    const float* cur = dir ? g_pB : g_pA;
    float*       nxt = dir ? g_pA : g_pB;
    int i = blockIdx.x*blockDim.x + threadIdx.x;
    if (i < PTS_TOTAL/4) ((float4*)nxt)[i] = ((const float4*)cur)[i];
}
__global__ void copy_out_kernel(float* __restrict__ dst){
    int i = blockIdx.x*blockDim.x + threadIdx.x;
    if (i < PTS_TOTAL/4) ((float4*)dst)[i] = ((const float4*)g_pA)[i];
}

// ---------------- fold Wf2 @ W0_feat -----------------------------------------
__global__ void mm_kernel(const float* __restrict__ Wf2, const float* __restrict__ W0,
                          const float* __restrict__ b0, const float* __restrict__ bf2){
    int i = blockIdx.x, j = threadIdx.x;
    if (i < FDIM){
        float a = 0.f;
        for (int c = 0; c < FDIM; c++) a = fmaf(Wf2[i*FDIM+c], W0[(3+c)*FDIM + j], a);
        g_M[i*FDIM+j] = a;
    } else {
        float a = b0[j];
        for (int c = 0; c < FDIM; c++) a = fmaf(bf2[c], W0[(3+c)*FDIM + j], a);
        g_cvec[j] = a;
    }
}

// ---------------- prep: WbT bf16 (BT[l][n][k] = Wb[l][k][n]) -----------------
__global__ void prep_b_kernel(const float* __restrict__ Wb){
    int lay = blockIdx.x >> 7, n = blockIdx.x & 127, k = threadIdx.x;
    g_BT[(lay*FDIM + n)*PIT + k] = __float2bfloat16(Wb[(lay*FDIM + k)*FDIM + n]);
}

// ---------------- precompute: pre = relu(pcl@Wf1+bf1) @ M + cvec -------------
__global__ __launch_bounds__(256) void precomp_kernel(
    const float* __restrict__ pcl, const float* __restrict__ Wf1,
    const float* __restrict__ bf1)
{
    extern __shared__ float sm[];
    float* sW  = sm;
    float* sh1 = sm + FDIM*FDIM;
    int tid = threadIdx.x, wid = tid >> 5, lane = tid & 31;

    for (int i = tid; i < FDIM*FDIM/4; i += blockDim.x)
        ((float4*)sW)[i] = ((const float4*)g_M)[i];
    __syncthreads();

    float4 cvv  = *(const float4*)(g_cvec + lane*4);
    float4 bf1v = *(const float4*)(bf1 + lane*4);
    float4 w0 = *(const float4*)(Wf1 + 0*FDIM + lane*4);
    float4 w1 = *(const float4*)(Wf1 + 1*FDIM + lane*4);
    float4 w2 = *(const float4*)(Wf1 + 2*FDIM + lane*4);
    float* myh = sh1 + wid*FDIM;

    int gw = blockIdx.x*(blockDim.x >> 5) + wid;
    int stride = gridDim.x*(blockDim.x >> 5);
    for (int r = gw; r < BN; r += stride){
        float x0 = pcl[r*3+0], x1 = pcl[r*3+1], x2 = pcl[r*3+2];
        float4 h;
        h.x = fmaxf(fmaf(x0,w0.x, fmaf(x1,w1.x, fmaf(x2,w2.x, bf1v.x))), 0.f);
        h.y = fmaxf(fmaf(x0,w0.y, fmaf(x1,w1.y, fmaf(x2,w2.y, bf1v.y))), 0.f);
        h.z = fmaxf(fmaf(x0,w0.z, fmaf(x1,w1.z, fmaf(x2,w2.z, bf1v.z))), 0.f);
        h.w = fmaxf(fmaf(x0,w0.w, fmaf(x1,w1.w, fmaf(x2,w2.w, bf1v.w))), 0.f);
        __syncwarp();
        *(float4*)(myh + lane*4) = h;
        __syncwarp();
        u64 a01, a23;
        asm("mov.b64 %0, {%1, %2};" : "=l"(a01) : "r"(__float_as_uint(cvv.x)), "r"(__float_as_uint(cvv.y)));
        asm("mov.b64 %0, {%1, %2};" : "=l"(a23) : "r"(__float_as_uint(cvv.z)), "r"(__float_as_uint(cvv.w)));
        #pragma unroll 8
        for (int c = 0; c < 32; c++){
            float4 h4 = *(float4*)(myh + c*4);
            const float* wr = sW + (c*4)*FDIM + lane*4;
            ulonglong2 q0 = *(const ulonglong2*)(wr);
            ulonglong2 q1 = *(const ulonglong2*)(wr + FDIM);
            ulonglong2 q2 = *(const ulonglong2*)(wr + 2*FDIM);
            ulonglong2 q3 = *(const ulonglong2*)(wr + 3*FDIM);
            u64 s0 = splat2(h4.x), s1 = splat2(h4.y), s2 = splat2(h4.z), s3 = splat2(h4.w);
            a01 = fma2(s0, q0.x, a01); a23 = fma2(s0, q0.y, a23);
            a01 = fma2(s1, q1.x, a01); a23 = fma2(s1, q1.y, a23);
            a01 = fma2(s2, q2.x, a01); a23 = fma2(s2, q2.y, a23);
            a01 = fma2(s3, q3.x, a01); a23 = fma2(s3, q3.y, a23);
        }
        float2 r01 = unpack2(a01), r23 = unpack2(a23);
        *(float4*)(g_pre + r*FDIM + lane*4) = make_float4(r01.x, r01.y, r23.x, r23.y);
    }
}

// ---------------- HMMA step kernel -------------------------------------------
// 512 thr = 2 warpgroups of 8 warps; each wg owns one 128-row tile.
// Warp tile 32m x 64n (4m x 2n warps) -> B smem traffic halved vs 16x64.
#define SM_BT 0                       // 2 x 128 x 136 bf16 = 69632
#define SM_A  69632                   // 4 buffers (wg0:A0,A1 wg1:A0,A1) x 34816
#define SM_WX (69632 + 4*34816)       // 208896: 3 x 128 f32
#define SM_WO (SM_WX+1536)
#define SM_BB (SM_WO+1536)
#define STEP_SMEM (SM_BB+1024)        // 212992

__device__ __forceinline__ void gemm_128_v2(u32 aLd0, u32 aLd1, u32 bLd,
                                            float acc[2][8][4]){
    #pragma unroll
    for (int kk = 0; kk < 8; kk++){
        u32 a0,a1,a2,a3, c0,c1,c2,c3;
        ldsm_x4(aLd0 + kk*32, a0,a1,a2,a3);
        ldsm_x4(aLd1 + kk*32, c0,c1,c2,c3);
        #pragma unroll
        for (int np = 0; np < 4; np++){
            u32 b0,b1,b2,b3;
            ldsm_x4(bLd + np*(16*PIT*2) + kk*32, b0,b1,b2,b3);
            mma16816(acc[0][2*np],   a0,a1,a2,a3, b0,b1);
            mma16816(acc[0][2*np+1], a0,a1,a2,a3, b2,b3);
            mma16816(acc[1][2*np],   c0,c1,c2,c3, b0,b1);
            mma16816(acc[1][2*np+1], c0,c1,c2,c3, b2,b3);
        }
    }
}

__global__ __launch_bounds__(512, 1) void step_mma_kernel(
    const float* __restrict__ pcl_noisy, const float* __restrict__ W0,
    const float* __restrict__ Wo, const float* __restrict__ bo,
    const float* __restrict__ bb, float s, int dir)
{
    extern __shared__ char smem[];
    u32 sb = smem_u32(smem);
    int tid = threadIdx.x, wg = tid >> 8, w8 = (tid >> 5) & 7, l = tid & 31;
    int wm = w8 & 3, wn = w8 >> 2;
    const float* cur = dir ? g_pB : g_pA;
    float*       nxt = dir ? g_pA : g_pB;

    for (int i = tid; i < 69632/16; i += 512)
        ((float4*)(smem+SM_BT))[i] = ((const float4*)g_BT)[i];
    for (int i = tid; i < 384; i += 512) ((float*)(smem+SM_WX))[i] = W0[i];
    if (tid < 128){
        float* wo = (float*)(smem+SM_WO);
        wo[tid] = Wo[tid*3]; wo[128+tid] = Wo[tid*3+1]; wo[256+tid] = Wo[tid*3+2];
    }
    if ((tid & 256) == 0 && tid < 256) ((float*)(smem+SM_BB))[tid] = bb[tid];
    __syncthreads();

    const float* sWx = (const float*)(smem+SM_WX);
    const float* sWo = (const float*)(smem+SM_WO);
    const float* sBB = (const float*)(smem+SM_BB);
    float bo0 = bo[0], bo1 = bo[1], bo2 = bo[2];

    // layer0 invariants (lane covers cols 4l..4l+3)
    float4 wa  = *(const float4*)(sWx + 4*l);
    float4 wbv = *(const float4*)(sWx + 128 + 4*l);
    float4 wc  = *(const float4*)(sWx + 256 + 4*l);

    u32 a0base = sb + SM_A + (u32)(wg*2*34816);
    u32 a1base = a0base + 34816;
    // A ldmatrix addrs (16-row sub-tiles mt=0,1)
    u32 aLd0 = a0base + (u32)(((32*wm + (l & 15))*PIT + 8*(l >> 4)) * 2);
    u32 aLd0b = aLd0 + 16*PIT*2;
    u32 aLd1 = aLd0 + 34816, aLd1b = aLd0b + 34816;
    // B ldmatrix addr (x4 spans 16 n-rows: two 8-col n-tiles)
    u32 bLd = sb + SM_BT + (u32)((((wn << 6) + ((l >> 4) << 3) + (l & 7))*PIT
                                  + 8*((l >> 3) & 1)) * 2);
    int barid = 1 + wg;
    // epilogue coords
    int cb = (wn << 6) + 2*(l & 3);       // lane's first col (+8 per nt)
    int rq = l >> 2;                      // row within 16-row sub-tile (and +8)

    for (int it = 0; it < 4; ++it){
        int tile = it*296 + (blockIdx.x << 1) + wg;
        if (tile >= NTILES) break;

        // ---- layer 0: warp covers 4 groups = 16 rows ----
        {
            int g0 = (tile << 5) + (w8 << 2);
            #pragma unroll
            for (int gg = 0; gg < 4; gg++){
                int g = g0 + gg;
                int b = g >> 14, n = g & (NPTS-1);
                const float* cen = pcl_noisy + 3*g;
                float p0 = cen[0], p1 = cen[1], p2 = cen[2];
                float4 pv = *(const float4*)(g_pre + (g << 7) + 4*l);
                #pragma unroll
                for (int k = 0; k < 4; k++){
                    int nb = n + k - 2; nb = nb < 0 ? 0 : (nb > NPTS-1 ? NPTS-1 : nb);
                    const float* pc = cur + 3*((b << 14) | nb);
                    float x0 = pc[0]-p0, x1 = pc[1]-p1, x2 = pc[2]-p2;
                    float y0 = fmaxf(pv.x + x0*wa.x + x1*wbv.x + x2*wc.x, 0.f);
                    float y1 = fmaxf(pv.y + x0*wa.y + x1*wbv.y + x2*wc.y, 0.f);
                    float y2 = fmaxf(pv.z + x0*wa.z + x1*wbv.z + x2*wc.z, 0.f);
                    float y3 = fmaxf(pv.w + x0*wa.w + x1*wbv.w + x2*wc.w, 0.f);
                    __nv_bfloat162 pa = __floats2bfloat162_rn(y0, y1);
                    __nv_bfloat162 pb2 = __floats2bfloat162_rn(y2, y3);
                    int row = (w8 << 4) + (gg << 2) + k;
                    *(uint2*)((char*)smem + (a0base - sb) + (row*PIT + 4*l)*2) =
                        make_uint2(*(u32*)&pa, *(u32*)&pb2);
                }
            }
        }
        asm volatile("bar.sync %0, 256;" :: "r"(barid) : "memory");

        // ---- GEMM 1: acc = A0 @ Wb0^T ----
        float acc[2][8][4];
        #pragma unroll
        for (int mt = 0; mt < 2; mt++)
            #pragma unroll
            for (int nt = 0; nt < 8; nt++){
                acc[mt][nt][0]=0.f; acc[mt][nt][1]=0.f; acc[mt][nt][2]=0.f; acc[mt][nt][3]=0.f;
            }
        gemm_128_v2(aLd0, aLd0b, bLd, acc);

        // ---- epilogue 1: h1 = h0 + relu(acc + bb0) -> A1 ----
        #pragma unroll
        for (int mt = 0; mt < 2; mt++){
            int r0 = (wm << 5) + (mt << 4) + rq;
            #pragma unroll
            for (int nt = 0; nt < 8; nt++){
                int c = cb + nt*8;
                float bbx = sBB[c], bby = sBB[c+1];
                int offA = (r0*PIT + c)*2, offB = ((r0+8)*PIT + c)*2;
                float2 h0a = __bfloat1622float2(*(__nv_bfloat162*)((char*)smem + (a0base-sb) + offA));
                float2 h0b = __bfloat1622float2(*(__nv_bfloat162*)((char*)smem + (a0base-sb) + offB));
                float v0 = h0a.x + fmaxf(acc[mt][nt][0] + bbx, 0.f);
                float v1 = h0a.y + fmaxf(acc[mt][nt][1] + bby, 0.f);
                float v2 = h0b.x + fmaxf(acc[mt][nt][2] + bbx, 0.f);
                float v3 = h0b.y + fmaxf(acc[mt][nt][3] + bby, 0.f);
                *(__nv_bfloat162*)((char*)smem + (a1base-sb) + offA) = __floats2bfloat162_rn(v0, v1);
                *(__nv_bfloat162*)((char*)smem + (a1base-sb) + offB) = __floats2bfloat162_rn(v2, v3);
            }
        }
        asm volatile("bar.sync %0, 256;" :: "r"(barid) : "memory");

        // ---- GEMM 2: acc = A1 @ Wb1^T ----
        #pragma unroll
        for (int mt = 0; mt < 2; mt++)
            #pragma unroll
            for (int nt = 0; nt < 8; nt++){
                acc[mt][nt][0]=0.f; acc[mt][nt][1]=0.f; acc[mt][nt][2]=0.f; acc[mt][nt][3]=0.f;
            }
        gemm_128_v2(aLd1, aLd1b, bLd + 34816, acc);   // layer 1 B at +34816

        // ---- epilogue 2: h2 = h1 + relu(acc + bb1), fused 128->3 projection
        float sum[2][2][3];
        #pragma unroll
        for (int mt = 0; mt < 2; mt++)
            #pragma unroll
            for (int hh = 0; hh < 2; hh++){ sum[mt][hh][0]=0.f; sum[mt][hh][1]=0.f; sum[mt][hh][2]=0.f; }
        #pragma unroll
        for (int mt = 0; mt < 2; mt++){
            int r0 = (wm << 5) + (mt << 4) + rq;
            #pragma unroll
            for (int nt = 0; nt < 8; nt++){
                int c = cb + nt*8;
                float bbx = sBB[128+c], bby = sBB[128+c+1];
                int offA = (r0*PIT + c)*2, offB = ((r0+8)*PIT + c)*2;
                float2 h1a = __bfloat1622float2(*(__nv_bfloat162*)((char*)smem + (a1base-sb) + offA));
                float2 h1b = __bfloat1622float2(*(__nv_bfloat162*)((char*)smem + (a1base-sb) + offB));
                float v0 = h1a.x + fmaxf(acc[mt][nt][0] + bbx, 0.f);
                float v1 = h1a.y + fmaxf(acc[mt][nt][1] + bby, 0.f);
                float v2 = h1b.x + fmaxf(acc[mt][nt][2] + bbx, 0.f);
                float v3 = h1b.y + fmaxf(acc[mt][nt][3] + bby, 0.f);
                float w0x = sWo[c],     w0y = sWo[c+1];
                float w1x = sWo[128+c], w1y = sWo[128+c+1];
                float w2x = sWo[256+c], w2y = sWo[256+c+1];
                sum[mt][0][0] += v0*w0x + v1*w0y;
                sum[mt][0][1] += v0*w1x + v1*w1y;
                sum[mt][0][2] += v0*w2x + v1*w2y;
                sum[mt][1][0] += v2*w0x + v3*w0y;
                sum[mt][1][1] += v2*w1x + v3*w1y;
                sum[mt][1][2] += v2*w2x + v3*w2y;
            }
        }
        #pragma unroll
        for (int off = 1; off <= 2; off <<= 1)
            #pragma unroll
            for (int mt = 0; mt < 2; mt++)
                #pragma unroll
                for (int hh = 0; hh < 2; hh++){
                    sum[mt][hh][0] += __shfl_xor_sync(0xffffffffu, sum[mt][hh][0], off);
                    sum[mt][hh][1] += __shfl_xor_sync(0xffffffffu, sum[mt][hh][1], off);
                    sum[mt][hh][2] += __shfl_xor_sync(0xffffffffu, sum[mt][hh][2], off);
                }
        if ((l & 3) == 0){
            float bx = wn ? 0.f : bo0, by = wn ? 0.f : bo1, bz = wn ? 0.f : bo2;
            #pragma unroll
            for (int mt = 0; mt < 2; mt++)
                #pragma unroll
                for (int hh = 0; hh < 2; hh++){
                    int row = (wm << 5) + (mt << 4) + rq + (hh << 3);
                    int g = (tile << 5) + (row >> 2);
                    int b = g >> 14, n = g & (NPTS-1), k = row & 3;
                    int nb = n + k - 2; nb = nb < 0 ? 0 : (nb > NPTS-1 ? NPTS-1 : nb);
                    float* dst = nxt + 3*((b << 14) | nb);
                    atomicAdd(dst + 0, s*(sum[mt][hh][0] + bx));
                    atomicAdd(dst + 1, s*(sum[mt][hh][1] + by));
                    atomicAdd(dst + 2, s*(sum[mt][hh][2] + bz));
                }
        }
    }
}

// ---------------------------------------------------------------------------
extern "C" void kernel_launch(void* const* d_in, const int* in_sizes, int n_in,
                              void* d_out, int out_size)
{
    const float* pcl = (const float*)d_in[0];
    const float* Wf1 = (const float*)d_in[1];
    const float* bf1 = (const float*)d_in[2];
    const float* Wf2 = (const float*)d_in[3];
    const float* bf2 = (const float*)d_in[4];
    const float* W0  = (const float*)d_in[5];
    const float* b0  = (const float*)d_in[6];
    const float* Wb  = (const float*)d_in[7];
    const float* bb  = (const float*)d_in[8];
    const float* Wo  = (const float*)d_in[9];
    const float* bo  = (const float*)d_in[10];

    size_t pre_smem = (size_t)(FDIM*FDIM + 8*FDIM) * sizeof(float);
    cudaFuncSetAttribute(precomp_kernel, cudaFuncAttributeMaxDynamicSharedMemorySize, (int)pre_smem);
    cudaFuncSetAttribute(step_mma_kernel, cudaFuncAttributeMaxDynamicSharedMemorySize, STEP_SMEM);

    mm_kernel<<<FDIM+1, FDIM>>>(Wf2, W0, b0, bf2);
    prep_b_kernel<<<256, 128>>>(Wb);
    precomp_kernel<<<148, 256, pre_smem>>>(pcl, Wf1, bf1);
    copy_in_kernel<<<PTS_TOTAL/4/256, 256>>>(pcl);

    float s = 0.2f;
    for (int i = 0; i < 4; i++){
        if (i) copy_ping_kernel<<<PTS_TOTAL/4/256, 256>>>(i & 1);
        step_mma_kernel<<<148, 512, STEP_SMEM>>>(pcl, W0, Wo, bo, bb, s, i & 1);
        s *= 0.95f;
    }
    // dir sequence 0,1,0,1 -> final result in g_pA
    copy_out_kernel<<<PTS_TOTAL/4/256, 256>>>((float*)d_out);
}

// round 10
// speedup vs baseline: 4.7436x; 1.0214x over previous
#include <cuda_runtime.h>
#include <cuda_bf16.h>

#define BATCH 2
#define NPTS  16384
#define FDIM  128
#define BN    (BATCH*NPTS)           // 32768 groups
#define PTS_TOTAL (BATCH*NPTS*3)     // 98304 floats
#define NT64  2048                   // 131072 rows / 64-row tiles
#define PIT   136                    // bf16 row pitch (272B: conflict-free ldmatrix)
typedef unsigned int u32;
typedef unsigned long long u64;

// ---------------- low-level helpers -----------------------------------------
__device__ __forceinline__ u32 smem_u32(const void* p){
    u32 a; asm("{ .reg .u64 t; cvta.to.shared.u64 t, %1; cvt.u32.u64 %0, t; }"
               : "=r"(a) : "l"(p));
    return a;
}
__device__ __forceinline__ void ldsm_x4(u32 a, u32& r0, u32& r1, u32& r2, u32& r3){
    asm volatile("ldmatrix.sync.aligned.m8n8.x4.shared.b16 {%0,%1,%2,%3}, [%4];"
                 : "=r"(r0),"=r"(r1),"=r"(r2),"=r"(r3) : "r"(a));
}
__device__ __forceinline__ void mma16816(float* c, u32 a0, u32 a1, u32 a2, u32 a3,
                                         u32 b0, u32 b1){
    asm volatile("mma.sync.aligned.m16n8k16.row.col.f32.bf16.bf16.f32 "
                 "{%0,%1,%2,%3}, {%4,%5,%6,%7}, {%8,%9}, {%0,%1,%2,%3};"
                 : "+f"(c[0]),"+f"(c[1]),"+f"(c[2]),"+f"(c[3])
                 : "r"(a0),"r"(a1),"r"(a2),"r"(a3),"r"(b0),"r"(b1));
}
// f32x2 helpers (precomp kernel)
__device__ __forceinline__ u64 splat2(float x){
    u64 r; asm("mov.b64 %0, {%1, %1};" : "=l"(r) : "r"(__float_as_uint(x))); return r;
}
__device__ __forceinline__ u64 fma2(u64 a, u64 b, u64 c){
    u64 d; asm("fma.rn.f32x2 %0, %1, %2, %3;" : "=l"(d) : "l"(a), "l"(b), "l"(c)); return d;
}
__device__ __forceinline__ float2 unpack2(u64 v){
    u32 lo, hi; asm("mov.b64 {%0, %1}, %2;" : "=r"(lo), "=r"(hi) : "l"(v));
    return make_float2(__uint_as_float(lo), __uint_as_float(hi));
}

// ---------------- scratch ----------------------------------------------------
__device__ float  g_pre[BN*FDIM];     // feat@W0f + b0 (precomputed, 16MB)
__device__ float  g_M[FDIM*FDIM];
__device__ float  g_cvec[FDIM];
__device__ float  g_pA[PTS_TOTAL];
__device__ float  g_pB[PTS_TOTAL];
__device__ __nv_bfloat16 g_BT[2*FDIM*PIT];   // WbT bf16, pitch 136

// ---------------- copies -----------------------------------------------------
__global__ void copy_in_kernel(const float* __restrict__ src){
    int i = blockIdx.x*blockDim.x + threadIdx.x;
    if (i < PTS_TOTAL/4){ float4 v = ((const float4*)src)[i]; ((float4*)g_pA)[i]=v; ((float4*)g_pB)[i]=v; }
}
__global__ void copy_ping_kernel(int dir){
    const float* cur = dir ? g_pB : g_pA;
    float*       nxt = dir ? g_pA : g_pB;
    int i = blockIdx.x*blockDim.x + threadIdx.x;
    if (i < PTS_TOTAL/4) ((float4*)nxt)[i] = ((const float4*)cur)[i];
}
__global__ void copy_out_kernel(float* __restrict__ dst){
    int i = blockIdx.x*blockDim.x + threadIdx.x;
    if (i < PTS_TOTAL/4) ((float4*)dst)[i] = ((const float4*)g_pA)[i];
}

// ---------------- fold Wf2 @ W0_feat -----------------------------------------
__global__ void mm_kernel(const float* __restrict__ Wf2, const float* __restrict__ W0,
                          const float* __restrict__ b0, const float* __restrict__ bf2){
    int i = blockIdx.x, j = threadIdx.x;
    if (i < FDIM){
        float a = 0.f;
        for (int c = 0; c < FDIM; c++) a = fmaf(Wf2[i*FDIM+c], W0[(3+c)*FDIM + j], a);
        g_M[i*FDIM+j] = a;
    } else {
        float a = b0[j];
        for (int c = 0; c < FDIM; c++) a = fmaf(bf2[c], W0[(3+c)*FDIM + j], a);
        g_cvec[j] = a;
    }
}

// ---------------- prep: WbT bf16 (BT[l][n][k] = Wb[l][k][n]) -----------------
__global__ void prep_b_kernel(const float* __restrict__ Wb){
    int lay = blockIdx.x >> 7, n = blockIdx.x & 127, k = threadIdx.x;
    g_BT[(lay*FDIM + n)*PIT + k] = __float2bfloat16(Wb[(lay*FDIM + k)*FDIM + n]);
}

// ---------------- precompute: pre = relu(pcl@Wf1+bf1) @ M + cvec -------------
__global__ __launch_bounds__(256) void precomp_kernel(
    const float* __restrict__ pcl, const float* __restrict__ Wf1,
    const float* __restrict__ bf1)
{
    extern __shared__ float sm[];
    float* sW  = sm;
    float* sh1 = sm + FDIM*FDIM;
    int tid = threadIdx.x, wid = tid >> 5, lane = tid & 31;

    for (int i = tid; i < FDIM*FDIM/4; i += blockDim.x)
        ((float4*)sW)[i] = ((const float4*)g_M)[i];
    __syncthreads();

    float4 cvv  = *(const float4*)(g_cvec + lane*4);
    float4 bf1v = *(const float4*)(bf1 + lane*4);
    float4 w0 = *(const float4*)(Wf1 + 0*FDIM + lane*4);
    float4 w1 = *(const float4*)(Wf1 + 1*FDIM + lane*4);
    float4 w2 = *(const float4*)(Wf1 + 2*FDIM + lane*4);
    float* myh = sh1 + wid*FDIM;

    int gw = blockIdx.x*(blockDim.x >> 5) + wid;
    int stride = gridDim.x*(blockDim.x >> 5);
    for (int r = gw; r < BN; r += stride){
        float x0 = pcl[r*3+0], x1 = pcl[r*3+1], x2 = pcl[r*3+2];
        float4 h;
        h.x = fmaxf(fmaf(x0,w0.x, fmaf(x1,w1.x, fmaf(x2,w2.x, bf1v.x))), 0.f);
        h.y = fmaxf(fmaf(x0,w0.y, fmaf(x1,w1.y, fmaf(x2,w2.y, bf1v.y))), 0.f);
        h.z = fmaxf(fmaf(x0,w0.z, fmaf(x1,w1.z, fmaf(x2,w2.z, bf1v.z))), 0.f);
        h.w = fmaxf(fmaf(x0,w0.w, fmaf(x1,w1.w, fmaf(x2,w2.w, bf1v.w))), 0.f);
        __syncwarp();
        *(float4*)(myh + lane*4) = h;
        __syncwarp();
        u64 a01, a23;
        asm("mov.b64 %0, {%1, %2};" : "=l"(a01) : "r"(__float_as_uint(cvv.x)), "r"(__float_as_uint(cvv.y)));
        asm("mov.b64 %0, {%1, %2};" : "=l"(a23) : "r"(__float_as_uint(cvv.z)), "r"(__float_as_uint(cvv.w)));
        #pragma unroll 8
        for (int c = 0; c < 32; c++){
            float4 h4 = *(float4*)(myh + c*4);
            const float* wr = sW + (c*4)*FDIM + lane*4;
            ulonglong2 q0 = *(const ulonglong2*)(wr);
            ulonglong2 q1 = *(const ulonglong2*)(wr + FDIM);
            ulonglong2 q2 = *(const ulonglong2*)(wr + 2*FDIM);
            ulonglong2 q3 = *(const ulonglong2*)(wr + 3*FDIM);
            u64 s0 = splat2(h4.x), s1 = splat2(h4.y), s2 = splat2(h4.z), s3 = splat2(h4.w);
            a01 = fma2(s0, q0.x, a01); a23 = fma2(s0, q0.y, a23);
            a01 = fma2(s1, q1.x, a01); a23 = fma2(s1, q1.y, a23);
            a01 = fma2(s2, q2.x, a01); a23 = fma2(s2, q2.y, a23);
            a01 = fma2(s3, q3.x, a01); a23 = fma2(s3, q3.y, a23);
        }
        float2 r01 = unpack2(a01), r23 = unpack2(a23);
        *(float4*)(g_pre + r*FDIM + lane*4) = make_float4(r01.x, r01.y, r23.x, r23.y);
    }
}

// ---------------- HMMA step kernel -------------------------------------------
// 512 thr = 2 warpgroups of 8 warps; each wg owns one 64-row tile (16 groups).
// Warp tile 16m x 64n (4m x 2n warps). 2048 tiles / 296 wg-slots = ~7 even rounds.
#define SM_BT 0                       // 2 x 128 x 136 bf16 = 69632
#define SM_A  69632                   // 4 buffers (wg0:A0,A1 wg1:A0,A1) x 17408
#define SM_WX (69632 + 4*17408)       // 139264: 3 x 128 f32
#define SM_WO (SM_WX+1536)
#define SM_BB (SM_WO+1536)
#define STEP_SMEM (SM_BB+1024)        // 143360

__device__ __forceinline__ void gemm_64(u32 aLd, u32 bLd, float acc[8][4]){
    #pragma unroll
    for (int kk = 0; kk < 8; kk++){
        u32 a0,a1,a2,a3;
        ldsm_x4(aLd + kk*32, a0,a1,a2,a3);
        #pragma unroll
        for (int np = 0; np < 4; np++){
            u32 b0,b1,b2,b3;
            ldsm_x4(bLd + np*(16*PIT*2) + kk*32, b0,b1,b2,b3);
            mma16816(acc[2*np],   a0,a1,a2,a3, b0,b1);
            mma16816(acc[2*np+1], a0,a1,a2,a3, b2,b3);
        }
    }
}

__global__ __launch_bounds__(512, 1) void step_mma_kernel(
    const float* __restrict__ pcl_noisy, const float* __restrict__ W0,
    const float* __restrict__ Wo, const float* __restrict__ bo,
    const float* __restrict__ bb, float s, int dir)
{
    extern __shared__ char smem[];
    u32 sb = smem_u32(smem);
    int tid = threadIdx.x, wg = tid >> 8, w8 = (tid >> 5) & 7, l = tid & 31;
    int wm = w8 & 3, wn = w8 >> 2;
    const float* cur = dir ? g_pB : g_pA;
    float*       nxt = dir ? g_pA : g_pB;

    for (int i = tid; i < 69632/16; i += 512)
        ((float4*)(smem+SM_BT))[i] = ((const float4*)g_BT)[i];
    for (int i = tid; i < 384; i += 512) ((float*)(smem+SM_WX))[i] = W0[i];
    if (tid < 128){
        float* wo = (float*)(smem+SM_WO);
        wo[tid] = Wo[tid*3]; wo[128+tid] = Wo[tid*3+1]; wo[256+tid] = Wo[tid*3+2];
    }
    if (tid < 256) ((float*)(smem+SM_BB))[tid] = bb[tid];
    __syncthreads();

    const float* sWx = (const float*)(smem+SM_WX);
    const float* sWo = (const float*)(smem+SM_WO);
    const float* sBB = (const float*)(smem+SM_BB);
    float bo0 = bo[0], bo1 = bo[1], bo2 = bo[2];

    // layer0 invariants (lane covers cols 4l..4l+3)
    float4 wa  = *(const float4*)(sWx + 4*l);
    float4 wbv = *(const float4*)(sWx + 128 + 4*l);
    float4 wc  = *(const float4*)(sWx + 256 + 4*l);

    u32 a0base = sb + SM_A + (u32)(wg*2*17408);
    u32 a1base = a0base + 17408;
    // A ldmatrix addr (16-row strip of this warp)
    u32 aLd0 = a0base + (u32)(((16*wm + (l & 15))*PIT + 8*(l >> 4)) * 2);
    u32 aLd1 = aLd0 + 17408;
    // B ldmatrix addr (x4 spans 16 n-rows: two 8-col n-tiles)
    u32 bLd = sb + SM_BT + (u32)((((wn << 6) + ((l >> 4) << 3) + (l & 7))*PIT
                                  + 8*((l >> 3) & 1)) * 2);
    int barid = 1 + wg;
    // epilogue coords
    int cb = (wn << 6) + 2*(l & 3);       // lane's first col (+8 per nt)
    int rq = l >> 2;                      // row within 16-row strip (and +8)
    int r0 = (wm << 4) + rq;

    for (int tile = (blockIdx.x << 1) + wg; tile < NT64; tile += 296){

        // ---- layer 0: warp covers 2 groups = 8 rows ----
        {
            int g0 = (tile << 4) + (w8 << 1);
            #pragma unroll
            for (int gg = 0; gg < 2; gg++){
                int g = g0 + gg;
                int b = g >> 14, n = g & (NPTS-1);
                const float* cen = pcl_noisy + 3*g;
                float p0 = cen[0], p1 = cen[1], p2 = cen[2];
                float4 pv = *(const float4*)(g_pre + (g << 7) + 4*l);
                #pragma unroll
                for (int k = 0; k < 4; k++){
                    int nb = n + k - 2; nb = nb < 0 ? 0 : (nb > NPTS-1 ? NPTS-1 : nb);
                    const float* pc = cur + 3*((b << 14) | nb);
                    float x0 = pc[0]-p0, x1 = pc[1]-p1, x2 = pc[2]-p2;
                    float y0 = fmaxf(pv.x + x0*wa.x + x1*wbv.x + x2*wc.x, 0.f);
                    float y1 = fmaxf(pv.y + x0*wa.y + x1*wbv.y + x2*wc.y, 0.f);
                    float y2 = fmaxf(pv.z + x0*wa.z + x1*wbv.z + x2*wc.z, 0.f);
                    float y3 = fmaxf(pv.w + x0*wa.w + x1*wbv.w + x2*wc.w, 0.f);
                    __nv_bfloat162 pa = __floats2bfloat162_rn(y0, y1);
                    __nv_bfloat162 pb2 = __floats2bfloat162_rn(y2, y3);
                    int row = (w8 << 3) + (gg << 2) + k;
                    *(uint2*)((char*)smem + (a0base - sb) + (row*PIT + 4*l)*2) =
                        make_uint2(*(u32*)&pa, *(u32*)&pb2);
                }
            }
        }
        asm volatile("bar.sync %0, 256;" :: "r"(barid) : "memory");

        // ---- GEMM 1: acc = A0 @ Wb0^T ----
        float acc[8][4];
        #pragma unroll
        for (int nt = 0; nt < 8; nt++){
            acc[nt][0]=0.f; acc[nt][1]=0.f; acc[nt][2]=0.f; acc[nt][3]=0.f;
        }
        gemm_64(aLd0, bLd, acc);

        // ---- epilogue 1: h1 = h0 + relu(acc + bb0) -> A1 ----
        #pragma unroll
        for (int nt = 0; nt < 8; nt++){
            int c = cb + nt*8;
            float bbx = sBB[c], bby = sBB[c+1];
            int offA = (r0*PIT + c)*2, offB = ((r0+8)*PIT + c)*2;
            float2 h0a = __bfloat1622float2(*(__nv_bfloat162*)((char*)smem + (a0base-sb) + offA));
            float2 h0b = __bfloat1622float2(*(__nv_bfloat162*)((char*)smem + (a0base-sb) + offB));
            float v0 = h0a.x + fmaxf(acc[nt][0] + bbx, 0.f);
            float v1 = h0a.y + fmaxf(acc[nt][1] + bby, 0.f);
            float v2 = h0b.x + fmaxf(acc[nt][2] + bbx, 0.f);
            float v3 = h0b.y + fmaxf(acc[nt][3] + bby, 0.f);
            *(__nv_bfloat162*)((char*)smem + (a1base-sb) + offA) = __floats2bfloat162_rn(v0, v1);
            *(__nv_bfloat162*)((char*)smem + (a1base-sb) + offB) = __floats2bfloat162_rn(v2, v3);
        }
        asm volatile("bar.sync %0, 256;" :: "r"(barid) : "memory");

        // ---- GEMM 2: acc = A1 @ Wb1^T ----
        #pragma unroll
        for (int nt = 0; nt < 8; nt++){
            acc[nt][0]=0.f; acc[nt][1]=0.f; acc[nt][2]=0.f; acc[nt][3]=0.f;
        }
        gemm_64(aLd1, bLd + 34816, acc);   // layer 1 B at +34816

        // ---- epilogue 2: h2 = h1 + relu(acc + bb1), fused 128->3 projection
        float sum[2][3];
        sum[0][0]=0.f; sum[0][1]=0.f; sum[0][2]=0.f;
        sum[1][0]=0.f; sum[1][1]=0.f; sum[1][2]=0.f;
        #pragma unroll
        for (int nt = 0; nt < 8; nt++){
            int c = cb + nt*8;
            float bbx = sBB[128+c], bby = sBB[128+c+1];
            int offA = (r0*PIT + c)*2, offB = ((r0+8)*PIT + c)*2;
            float2 h1a = __bfloat1622float2(*(__nv_bfloat162*)((char*)smem + (a1base-sb) + offA));
            float2 h1b = __bfloat1622float2(*(__nv_bfloat162*)((char*)smem + (a1base-sb) + offB));
            float v0 = h1a.x + fmaxf(acc[nt][0] + bbx, 0.f);
            float v1 = h1a.y + fmaxf(acc[nt][1] + bby, 0.f);
            float v2 = h1b.x + fmaxf(acc[nt][2] + bbx, 0.f);
            float v3 = h1b.y + fmaxf(acc[nt][3] + bby, 0.f);
            float w0x = sWo[c],     w0y = sWo[c+1];
            float w1x = sWo[128+c], w1y = sWo[128+c+1];
            float w2x = sWo[256+c], w2y = sWo[256+c+1];
            sum[0][0] += v0*w0x + v1*w0y;
            sum[0][1] += v0*w1x + v1*w1y;
            sum[0][2] += v0*w2x + v1*w2y;
            sum[1][0] += v2*w0x + v3*w0y;
            sum[1][1] += v2*w1x + v3*w1y;
            sum[1][2] += v2*w2x + v3*w2y;
        }
        #pragma unroll
        for (int off = 1; off <= 2; off <<= 1)
            #pragma unroll
            for (int hh = 0; hh < 2; hh++){
                sum[hh][0] += __shfl_xor_sync(0xffffffffu, sum[hh][0], off);
                sum[hh][1] += __shfl_xor_sync(0xffffffffu, sum[hh][1], off);
                sum[hh][2] += __shfl_xor_sync(0xffffffffu, sum[hh][2], off);
            }
        if ((l & 3) == 0){
            float bx = wn ? 0.f : bo0, by = wn ? 0.f : bo1, bz = wn ? 0.f : bo2;
            #pragma unroll
            for (int hh = 0; hh < 2; hh++){
                int row = r0 + (hh << 3);
                int g = (tile << 4) + (row >> 2);
                int b = g >> 14, n = g & (NPTS-1), k = row & 3;
                int nb = n + k - 2; nb = nb < 0 ? 0 : (nb > NPTS-1 ? NPTS-1 : nb);
                float* dst = nxt + 3*((b << 14) | nb);
                atomicAdd(dst + 0, s*(sum[hh][0] + bx));
                atomicAdd(dst + 1, s*(sum[hh][1] + by));
                atomicAdd(dst + 2, s*(sum[hh][2] + bz));
            }
        }
    }
}

// ---------------------------------------------------------------------------
extern "C" void kernel_launch(void* const* d_in, const int* in_sizes, int n_in,
                              void* d_out, int out_size)
{
    const float* pcl = (const float*)d_in[0];
    const float* Wf1 = (const float*)d_in[1];
    const float* bf1 = (const float*)d_in[2];
    const float* Wf2 = (const float*)d_in[3];
    const float* bf2 = (const float*)d_in[4];
    const float* W0  = (const float*)d_in[5];
    const float* b0  = (const float*)d_in[6];
    const float* Wb  = (const float*)d_in[7];
    const float* bb  = (const float*)d_in[8];
    const float* Wo  = (const float*)d_in[9];
    const float* bo  = (const float*)d_in[10];

    size_t pre_smem = (size_t)(FDIM*FDIM + 8*FDIM) * sizeof(float);
    cudaFuncSetAttribute(precomp_kernel, cudaFuncAttributeMaxDynamicSharedMemorySize, (int)pre_smem);
    cudaFuncSetAttribute(step_mma_kernel, cudaFuncAttributeMaxDynamicSharedMemorySize, STEP_SMEM);

    mm_kernel<<<FDIM+1, FDIM>>>(Wf2, W0, b0, bf2);
    prep_b_kernel<<<256, 128>>>(Wb);
    precomp_kernel<<<148, 256, pre_smem>>>(pcl, Wf1, bf1);
    copy_in_kernel<<<PTS_TOTAL/4/256, 256>>>(pcl);

    float s = 0.2f;
    for (int i = 0; i < 4; i++){
        if (i) copy_ping_kernel<<<PTS_TOTAL/4/256, 256>>>(i & 1);
        step_mma_kernel<<<148, 512, STEP_SMEM>>>(pcl, W0, Wo, bo, bb, s, i & 1);
        s *= 0.95f;
    }
    // dir sequence 0,1,0,1 -> final result in g_pA
    copy_out_kernel<<<PTS_TOTAL/4/256, 256>>>((float*)d_out);
}

// round 11
// speedup vs baseline: 6.4187x; 1.3531x over previous
#include <cuda_runtime.h>
#include <cuda_bf16.h>

#define BATCH 2
#define NPTS  16384
#define FDIM  128
#define BN    (BATCH*NPTS)           // 32768 groups
#define PTS_TOTAL (BATCH*NPTS*3)     // 98304 floats
#define NT64  2048                   // 131072 rows / 64-row tiles
#define PIT   136                    // bf16 row pitch (272B: conflict-free ldmatrix)
typedef unsigned int u32;

// ---------------- low-level helpers -----------------------------------------
__device__ __forceinline__ u32 smem_u32(const void* p){
    u32 a; asm("{ .reg .u64 t; cvta.to.shared.u64 t, %1; cvt.u32.u64 %0, t; }"
               : "=r"(a) : "l"(p));
    return a;
}
__device__ __forceinline__ void ldsm_x4(u32 a, u32& r0, u32& r1, u32& r2, u32& r3){
    asm volatile("ldmatrix.sync.aligned.m8n8.x4.shared.b16 {%0,%1,%2,%3}, [%4];"
                 : "=r"(r0),"=r"(r1),"=r"(r2),"=r"(r3) : "r"(a));
}
__device__ __forceinline__ void mma16816(float* c, u32 a0, u32 a1, u32 a2, u32 a3,
                                         u32 b0, u32 b1){
    asm volatile("mma.sync.aligned.m16n8k16.row.col.f32.bf16.bf16.f32 "
                 "{%0,%1,%2,%3}, {%4,%5,%6,%7}, {%8,%9}, {%0,%1,%2,%3};"
                 : "+f"(c[0]),"+f"(c[1]),"+f"(c[2]),"+f"(c[3])
                 : "r"(a0),"r"(a1),"r"(a2),"r"(a3),"r"(b0),"r"(b1));
}

// ---------------- scratch ----------------------------------------------------
__device__ float  g_pre[BN*FDIM];     // feat@W0f + b0 (precomputed, 16MB)
__device__ float  g_cvec[FDIM];
__device__ float  g_P0[PTS_TOTAL];
__device__ float  g_P1[PTS_TOTAL];
__device__ float  g_P2[PTS_TOTAL];
__device__ __nv_bfloat16 g_BT[2*FDIM*PIT];   // WbT bf16, pitch 136
__device__ __nv_bfloat16 g_MT[FDIM*PIT];     // (Wf2@W0f)^T bf16, pitch 136

__device__ __forceinline__ float* selbuf(int s_, const float* pcl, float* dout){
    if (s_ == 0) return g_P0;
    if (s_ == 1) return g_P1;
    if (s_ == 2) return g_P2;
    if (s_ == 4) return dout;
    return (float*)pcl;
}

// ---------------- fused prep: M^T, cvec, WbT ---------------------------------
__global__ void prep_fused(const float* __restrict__ Wf2, const float* __restrict__ W0,
                           const float* __restrict__ b0, const float* __restrict__ bf2,
                           const float* __restrict__ Wb){
    int bid = blockIdx.x, j = threadIdx.x;
    if (bid < 128){
        int i = bid;                    // k index
        float a = 0.f;
        for (int c = 0; c < FDIM; c++) a = fmaf(Wf2[i*FDIM+c], W0[(3+c)*FDIM + j], a);
        g_MT[j*PIT + i] = __float2bfloat16(a);   // MT[n][k] = M[k][n]
    } else if (bid == 128){
        float a = b0[j];
        for (int c = 0; c < FDIM; c++) a = fmaf(bf2[c], W0[(3+c)*FDIM + j], a);
        g_cvec[j] = a;
    } else {
        int b2 = bid - 129;             // 0..255
        int lay = b2 >> 7, n = b2 & 127, k = j;
        g_BT[(lay*FDIM + n)*PIT + k] = __float2bfloat16(Wb[(lay*FDIM + k)*FDIM + n]);
    }
}

// ---------------- HMMA precomp: pre = relu(X@Wf1+bf1) @ M + cvec -------------
#define PC_MT  0                      // 34816
#define PC_A   34816                  // 2 x 17408
#define PC_CON (34816 + 2*17408)      // 69632: Wf1(384) bf1(128) cvec(128) floats
#define PC_SMEM (PC_CON + 640*4)      // 72192

__device__ __forceinline__ void gemm_64(u32 aLd, u32 bLd, float acc[8][4]){
    #pragma unroll
    for (int kk = 0; kk < 8; kk++){
        u32 a0,a1,a2,a3;
        ldsm_x4(aLd + kk*32, a0,a1,a2,a3);
        #pragma unroll
        for (int np = 0; np < 4; np++){
            u32 b0,b1,b2,b3;
            ldsm_x4(bLd + np*(16*PIT*2) + kk*32, b0,b1,b2,b3);
            mma16816(acc[2*np],   a0,a1,a2,a3, b0,b1);
            mma16816(acc[2*np+1], a0,a1,a2,a3, b2,b3);
        }
    }
}

__global__ __launch_bounds__(512, 1) void precomp_hmma(
    const float* __restrict__ pcl, const float* __restrict__ Wf1,
    const float* __restrict__ bf1)
{
    extern __shared__ char smem[];
    u32 sb = smem_u32(smem);
    int tid = threadIdx.x, wg = tid >> 8, w8 = (tid >> 5) & 7, l = tid & 31;
    int wm = w8 & 3, wn = w8 >> 2;

    // zero P0 (scatter target of step 0)
    float4 z4 = make_float4(0.f,0.f,0.f,0.f);
    for (int i = blockIdx.x*512 + tid; i < PTS_TOTAL/4; i += 148*512)
        ((float4*)g_P0)[i] = z4;

    for (int i = tid; i < 34816/16; i += 512)
        ((float4*)smem)[i] = ((const float4*)g_MT)[i];
    float* con = (float*)(smem + PC_CON);
    if (tid < 384) con[tid] = Wf1[tid];
    if (tid >= 384) con[tid] = bf1[tid - 384];       // con[384..511]
    if (tid < 128) con[512 + tid] = g_cvec[tid];
    __syncthreads();

    const float* sWf = con;
    const float* sb1 = con + 384;
    const float* scv = con + 512;
    float4 f0 = *(const float4*)(sWf + 4*l);
    float4 f1 = *(const float4*)(sWf + 128 + 4*l);
    float4 f2 = *(const float4*)(sWf + 256 + 4*l);
    float4 b1v = *(const float4*)(sb1 + 4*l);

    u32 Abase = sb + PC_A + (u32)(wg*17408);
    u32 aLd = Abase + (u32)(((16*wm + (l & 15))*PIT + 8*(l >> 4)) * 2);
    u32 bLd = sb + PC_MT + (u32)((((wn << 6) + ((l >> 4) << 3) + (l & 7))*PIT
                                  + 8*((l >> 3) & 1)) * 2);
    int barid = 1 + wg;
    int cb = (wn << 6) + 2*(l & 3);
    int rq = l >> 2;
    int r0 = (wm << 4) + rq;

    for (int tile = (blockIdx.x << 1) + wg; tile < BN/64; tile += 296){
        // layer: h1 = relu(x@Wf1 + bf1); warp covers rows w8*8..+7, lane cols 4l..4l+3
        #pragma unroll
        for (int gg = 0; gg < 8; gg++){
            int gr = (tile << 6) + (w8 << 3) + gg;
            const float* xp = pcl + 3*gr;
            float x0 = xp[0], x1 = xp[1], x2 = xp[2];
            float y0 = fmaxf(fmaf(x0,f0.x, fmaf(x1,f1.x, fmaf(x2,f2.x, b1v.x))), 0.f);
            float y1 = fmaxf(fmaf(x0,f0.y, fmaf(x1,f1.y, fmaf(x2,f2.y, b1v.y))), 0.f);
            float y2 = fmaxf(fmaf(x0,f0.z, fmaf(x1,f1.z, fmaf(x2,f2.z, b1v.z))), 0.f);
            float y3 = fmaxf(fmaf(x0,f0.w, fmaf(x1,f1.w, fmaf(x2,f2.w, b1v.w))), 0.f);
            __nv_bfloat162 pa = __floats2bfloat162_rn(y0, y1);
            __nv_bfloat162 pb2 = __floats2bfloat162_rn(y2, y3);
            *(uint2*)((char*)smem + (Abase - sb) + ((((w8 << 3) + gg))*PIT + 4*l)*2) =
                make_uint2(*(u32*)&pa, *(u32*)&pb2);
        }
        asm volatile("bar.sync %0, 256;" :: "r"(barid) : "memory");

        float acc[8][4];
        #pragma unroll
        for (int nt = 0; nt < 8; nt++){
            acc[nt][0]=0.f; acc[nt][1]=0.f; acc[nt][2]=0.f; acc[nt][3]=0.f;
        }
        gemm_64(aLd, bLd, acc);

        int gr0 = (tile << 6) + r0;
        #pragma unroll
        for (int nt = 0; nt < 8; nt++){
            int c = cb + nt*8;
            *(float2*)(g_pre + (gr0 << 7) + c) =
                make_float2(acc[nt][0] + scv[c], acc[nt][1] + scv[c+1]);
            *(float2*)(g_pre + ((gr0 + 8) << 7) + c) =
                make_float2(acc[nt][2] + scv[c], acc[nt][3] + scv[c+1]);
        }
        asm volatile("bar.sync %0, 256;" :: "r"(barid) : "memory");
    }
}

// ---------------- HMMA step kernel -------------------------------------------
#define SM_BT 0                       // 2 x 128 x 136 bf16 = 69632
#define SM_A  69632                   // 4 buffers (wg0:A0,A1 wg1:A0,A1) x 17408
#define SM_WX (69632 + 4*17408)       // 139264: 3 x 128 f32
#define SM_WO (SM_WX+1536)
#define SM_BB (SM_WO+1536)
#define STEP_SMEM (SM_BB+1024)        // 143360

__global__ __launch_bounds__(512, 1) void step_mma_kernel(
    const float* __restrict__ pcl_noisy, const float* __restrict__ W0,
    const float* __restrict__ Wo, const float* __restrict__ bo,
    const float* __restrict__ bb, float s,
    int icur, int inxt, int izero, float* __restrict__ dout)
{
    extern __shared__ char smem[];
    u32 sb = smem_u32(smem);
    int tid = threadIdx.x, wg = tid >> 8, w8 = (tid >> 5) & 7, l = tid & 31;
    int wm = w8 & 3, wn = w8 >> 2;
    const float* cur = selbuf(icur, pcl_noisy, dout);
    float*       nxt = selbuf(inxt, pcl_noisy, dout);

    // zero the buffer that the NEXT step will scatter into
    if (izero >= 0){
        float4 z4 = make_float4(0.f,0.f,0.f,0.f);
        float* zb = selbuf(izero, pcl_noisy, dout);
        for (int i = blockIdx.x*512 + tid; i < PTS_TOTAL/4; i += 148*512)
            ((float4*)zb)[i] = z4;
    }

    for (int i = tid; i < 69632/16; i += 512)
        ((float4*)(smem+SM_BT))[i] = ((const float4*)g_BT)[i];
    for (int i = tid; i < 384; i += 512) ((float*)(smem+SM_WX))[i] = W0[i];
    if (tid < 128){
        float* wo = (float*)(smem+SM_WO);
        wo[tid] = Wo[tid*3]; wo[128+tid] = Wo[tid*3+1]; wo[256+tid] = Wo[tid*3+2];
    }
    if (tid < 256) ((float*)(smem+SM_BB))[tid] = bb[tid];
    __syncthreads();

    const float* sWx = (const float*)(smem+SM_WX);
    const float* sWo = (const float*)(smem+SM_WO);
    const float* sBB = (const float*)(smem+SM_BB);
    float bo0 = bo[0], bo1 = bo[1], bo2 = bo[2];

    float4 wa  = *(const float4*)(sWx + 4*l);
    float4 wbv = *(const float4*)(sWx + 128 + 4*l);
    float4 wc  = *(const float4*)(sWx + 256 + 4*l);

    u32 a0base = sb + SM_A + (u32)(wg*2*17408);
    u32 a1base = a0base + 17408;
    u32 aLd0 = a0base + (u32)(((16*wm + (l & 15))*PIT + 8*(l >> 4)) * 2);
    u32 aLd1 = aLd0 + 17408;
    u32 bLd = sb + SM_BT + (u32)((((wn << 6) + ((l >> 4) << 3) + (l & 7))*PIT
                                  + 8*((l >> 3) & 1)) * 2);
    int barid = 1 + wg;
    int cb = (wn << 6) + 2*(l & 3);
    int rq = l >> 2;
    int r0 = (wm << 4) + rq;

    for (int tile = (blockIdx.x << 1) + wg; tile < NT64; tile += 296){

        // ---- layer 0: warp covers 2 groups = 8 rows ----
        {
            int g0 = (tile << 4) + (w8 << 1);
            #pragma unroll
            for (int gg = 0; gg < 2; gg++){
                int g = g0 + gg;
                int b = g >> 14, n = g & (NPTS-1);
                const float* cen = pcl_noisy + 3*g;
                float p0 = cen[0], p1 = cen[1], p2 = cen[2];
                float4 pv = *(const float4*)(g_pre + (g << 7) + 4*l);
                #pragma unroll
                for (int k = 0; k < 4; k++){
                    int nb = n + k - 2; nb = nb < 0 ? 0 : (nb > NPTS-1 ? NPTS-1 : nb);
                    const float* pc = cur + 3*((b << 14) | nb);
                    float x0 = pc[0]-p0, x1 = pc[1]-p1, x2 = pc[2]-p2;
                    float y0 = fmaxf(pv.x + x0*wa.x + x1*wbv.x + x2*wc.x, 0.f);
                    float y1 = fmaxf(pv.y + x0*wa.y + x1*wbv.y + x2*wc.y, 0.f);
                    float y2 = fmaxf(pv.z + x0*wa.z + x1*wbv.z + x2*wc.z, 0.f);
                    float y3 = fmaxf(pv.w + x0*wa.w + x1*wbv.w + x2*wc.w, 0.f);
                    __nv_bfloat162 pa = __floats2bfloat162_rn(y0, y1);
                    __nv_bfloat162 pb2 = __floats2bfloat162_rn(y2, y3);
                    int row = (w8 << 3) + (gg << 2) + k;
                    *(uint2*)((char*)smem + (a0base - sb) + (row*PIT + 4*l)*2) =
                        make_uint2(*(u32*)&pa, *(u32*)&pb2);
                }
            }
        }
        asm volatile("bar.sync %0, 256;" :: "r"(barid) : "memory");

        // ---- GEMM 1: acc = A0 @ Wb0^T ----
        float acc[8][4];
        #pragma unroll
        for (int nt = 0; nt < 8; nt++){
            acc[nt][0]=0.f; acc[nt][1]=0.f; acc[nt][2]=0.f; acc[nt][3]=0.f;
        }
        gemm_64(aLd0, bLd, acc);

        // ---- epilogue 1: h1 = h0 + relu(acc + bb0) -> A1 ----
        #pragma unroll
        for (int nt = 0; nt < 8; nt++){
            int c = cb + nt*8;
            float bbx = sBB[c], bby = sBB[c+1];
            int offA = (r0*PIT + c)*2, offB = ((r0+8)*PIT + c)*2;
            float2 h0a = __bfloat1622float2(*(__nv_bfloat162*)((char*)smem + (a0base-sb) + offA));
            float2 h0b = __bfloat1622float2(*(__nv_bfloat162*)((char*)smem + (a0base-sb) + offB));
            float v0 = h0a.x + fmaxf(acc[nt][0] + bbx, 0.f);
            float v1 = h0a.y + fmaxf(acc[nt][1] + bby, 0.f);
            float v2 = h0b.x + fmaxf(acc[nt][2] + bbx, 0.f);
            float v3 = h0b.y + fmaxf(acc[nt][3] + bby, 0.f);
            *(__nv_bfloat162*)((char*)smem + (a1base-sb) + offA) = __floats2bfloat162_rn(v0, v1);
            *(__nv_bfloat162*)((char*)smem + (a1base-sb) + offB) = __floats2bfloat162_rn(v2, v3);
        }
        asm volatile("bar.sync %0, 256;" :: "r"(barid) : "memory");

        // ---- GEMM 2: acc = A1 @ Wb1^T ----
        #pragma unroll
        for (int nt = 0; nt < 8; nt++){
            acc[nt][0]=0.f; acc[nt][1]=0.f; acc[nt][2]=0.f; acc[nt][3]=0.f;
        }
        gemm_64(aLd1, bLd + 34816, acc);

        // ---- epilogue 2: h2 = h1 + relu(acc + bb1), fused 128->3 projection
        float sum[2][3];
        sum[0][0]=0.f; sum[0][1]=0.f; sum[0][2]=0.f;
        sum[1][0]=0.f; sum[1][1]=0.f; sum[1][2]=0.f;
        #pragma unroll
        for (int nt = 0; nt < 8; nt++){
            int c = cb + nt*8;
            float bbx = sBB[128+c], bby = sBB[128+c+1];
            int offA = (r0*PIT + c)*2, offB = ((r0+8)*PIT + c)*2;
            float2 h1a = __bfloat1622float2(*(__nv_bfloat162*)((char*)smem + (a1base-sb) + offA));
            float2 h1b = __bfloat1622float2(*(__nv_bfloat162*)((char*)smem + (a1base-sb) + offB));
            float v0 = h1a.x + fmaxf(acc[nt][0] + bbx, 0.f);
            float v1 = h1a.y + fmaxf(acc[nt][1] + bby, 0.f);
            float v2 = h1b.x + fmaxf(acc[nt][2] + bbx, 0.f);
            float v3 = h1b.y + fmaxf(acc[nt][3] + bby, 0.f);
            float w0x = sWo[c],     w0y = sWo[c+1];
            float w1x = sWo[128+c], w1y = sWo[128+c+1];
            float w2x = sWo[256+c], w2y = sWo[256+c+1];
            sum[0][0] += v0*w0x + v1*w0y;
            sum[0][1] += v0*w1x + v1*w1y;
            sum[0][2] += v0*w2x + v1*w2y;
            sum[1][0] += v2*w0x + v3*w0y;
            sum[1][1] += v2*w1x + v3*w1y;
            sum[1][2] += v2*w2x + v3*w2y;
        }
        #pragma unroll
        for (int off = 1; off <= 2; off <<= 1)
            #pragma unroll
            for (int hh = 0; hh < 2; hh++){
                sum[hh][0] += __shfl_xor_sync(0xffffffffu, sum[hh][0], off);
                sum[hh][1] += __shfl_xor_sync(0xffffffffu, sum[hh][1], off);
                sum[hh][2] += __shfl_xor_sync(0xffffffffu, sum[hh][2], off);
            }
        if ((l & 3) == 0){
            float bx = wn ? 0.f : bo0, by = wn ? 0.f : bo1, bz = wn ? 0.f : bo2;
            #pragma unroll
            for (int hh = 0; hh < 2; hh++){
                int row = r0 + (hh << 3);
                int g = (tile << 4) + (row >> 2);
                int b = g >> 14, n = g & (NPTS-1), k = row & 3;
                int nb = n + k - 2; nb = nb < 0 ? 0 : (nb > NPTS-1 ? NPTS-1 : nb);
                int didx = (b << 14) | nb;
                float* dst = nxt + 3*didx;
                // seed: exactly one row per point (n==nb at k==2, wn half 0)
                float sd0 = 0.f, sd1 = 0.f, sd2 = 0.f;
                if (wn == 0 && k == 2){
                    const float* cp = cur + 3*didx;
                    sd0 = cp[0]; sd1 = cp[1]; sd2 = cp[2];
                }
                atomicAdd(dst + 0, s*(sum[hh][0] + bx) + sd0);
                atomicAdd(dst + 1, s*(sum[hh][1] + by) + sd1);
                atomicAdd(dst + 2, s*(sum[hh][2] + bz) + sd2);
            }
        }
    }
}

// ---------------------------------------------------------------------------
extern "C" void kernel_launch(void* const* d_in, const int* in_sizes, int n_in,
                              void* d_out, int out_size)
{
    const float* pcl = (const float*)d_in[0];
    const float* Wf1 = (const float*)d_in[1];
    const float* bf1 = (const float*)d_in[2];
    const float* Wf2 = (const float*)d_in[3];
    const float* bf2 = (const float*)d_in[4];
    const float* W0  = (const float*)d_in[5];
    const float* b0  = (const float*)d_in[6];
    const float* Wb  = (const float*)d_in[7];
    const float* bb  = (const float*)d_in[8];
    const float* Wo  = (const float*)d_in[9];
    const float* bo  = (const float*)d_in[10];
    float* dout = (float*)d_out;

    cudaFuncSetAttribute(precomp_hmma, cudaFuncAttributeMaxDynamicSharedMemorySize, PC_SMEM);
    cudaFuncSetAttribute(step_mma_kernel, cudaFuncAttributeMaxDynamicSharedMemorySize, STEP_SMEM);

    prep_fused<<<385, 128>>>(Wf2, W0, b0, bf2, Wb);
    precomp_hmma<<<148, 512, PC_SMEM>>>(pcl, Wf1, bf1);   // also zeroes P0

    float s = 0.2f;
    // step0: read pcl(3) -> P0, zero P1
    step_mma_kernel<<<148, 512, STEP_SMEM>>>(pcl, W0, Wo, bo, bb, s, 3, 0, 1, dout);
    s *= 0.95f;
    // step1: P0 -> P1, zero P2
    step_mma_kernel<<<148, 512, STEP_SMEM>>>(pcl, W0, Wo, bo, bb, s, 0, 1, 2, dout);
    s *= 0.95f;
    // step2: P1 -> P2, zero d_out
    step_mma_kernel<<<148, 512, STEP_SMEM>>>(pcl, W0, Wo, bo, bb, s, 1, 2, 4, dout);
    s *= 0.95f;
    // step3: P2 -> d_out
    step_mma_kernel<<<148, 512, STEP_SMEM>>>(pcl, W0, Wo, bo, bb, s, 2, 4, -1, dout);
}

// round 13
// speedup vs baseline: 6.5114x; 1.0144x over previous
#include <cuda_runtime.h>
#include <cuda_bf16.h>

#define BATCH 2
#define NPTS  16384
#define FDIM  128
#define BN    (BATCH*NPTS)           // 32768 groups
#define PTS_TOTAL (BATCH*NPTS*3)     // 98304 floats
#define PIT   136                    // bf16 row pitch (272B: conflict-free ldmatrix)
#define NWT   8192                   // 131072 rows / 16-row warp tiles
typedef unsigned int u32;

// ---------------- low-level helpers -----------------------------------------
__device__ __forceinline__ u32 smem_u32(const void* p){
    u32 a; asm("{ .reg .u64 t; cvta.to.shared.u64 t, %1; cvt.u32.u64 %0, t; }"
               : "=r"(a) : "l"(p));
    return a;
}
__device__ __forceinline__ void ldsm_x4(u32 a, u32& r0, u32& r1, u32& r2, u32& r3){
    asm volatile("ldmatrix.sync.aligned.m8n8.x4.shared.b16 {%0,%1,%2,%3}, [%4];"
                 : "=r"(r0),"=r"(r1),"=r"(r2),"=r"(r3) : "r"(a));
}
__device__ __forceinline__ void mma16816(float* c, u32 a0, u32 a1, u32 a2, u32 a3,
                                         u32 b0, u32 b1){
    asm volatile("mma.sync.aligned.m16n8k16.row.col.f32.bf16.bf16.f32 "
                 "{%0,%1,%2,%3}, {%4,%5,%6,%7}, {%8,%9}, {%0,%1,%2,%3};"
                 : "+f"(c[0]),"+f"(c[1]),"+f"(c[2]),"+f"(c[3])
                 : "r"(a0),"r"(a1),"r"(a2),"r"(a3),"r"(b0),"r"(b1));
}
__device__ __forceinline__ u32 packbf(float x, float y){
    __nv_bfloat162 p = __floats2bfloat162_rn(x, y);
    return *(u32*)&p;
}
__device__ __forceinline__ float2 unpackbf(u32 v){
    return __bfloat1622float2(*(__nv_bfloat162*)&v);
}

// ---------------- scratch ----------------------------------------------------
__device__ float  g_pre[BN*FDIM];     // feat@W0f + b0 (precomputed, 16MB)
__device__ float  g_cvec[FDIM];
__device__ float  g_P0[PTS_TOTAL];
__device__ float  g_P1[PTS_TOTAL];
__device__ float  g_P2[PTS_TOTAL];
__device__ __nv_bfloat16 g_BT[2*FDIM*PIT];   // WbT bf16, pitch 136
__device__ __nv_bfloat16 g_MT[FDIM*PIT];     // (Wf2@W0f)^T bf16, pitch 136

__device__ __forceinline__ float* selbuf(int s_, const float* pcl, float* dout){
    if (s_ == 0) return g_P0;
    if (s_ == 1) return g_P1;
    if (s_ == 2) return g_P2;
    if (s_ == 4) return dout;
    return (float*)pcl;
}

// ---------------- fused prep: M^T, cvec, WbT ---------------------------------
__global__ void prep_fused(const float* __restrict__ Wf2, const float* __restrict__ W0,
                           const float* __restrict__ b0, const float* __restrict__ bf2,
                           const float* __restrict__ Wb){
    int bid = blockIdx.x, j = threadIdx.x;
    if (bid < 128){
        int i = bid;
        float a = 0.f;
        for (int c = 0; c < FDIM; c++) a = fmaf(Wf2[i*FDIM+c], W0[(3+c)*FDIM + j], a);
        g_MT[j*PIT + i] = __float2bfloat16(a);
    } else if (bid == 128){
        float a = b0[j];
        for (int c = 0; c < FDIM; c++) a = fmaf(bf2[c], W0[(3+c)*FDIM + j], a);
        g_cvec[j] = a;
    } else {
        int b2 = bid - 129;
        int lay = b2 >> 7, n = b2 & 127, k = j;
        g_BT[(lay*FDIM + n)*PIT + k] = __float2bfloat16(Wb[(lay*FDIM + k)*FDIM + n]);
    }
}

// ---------------- HMMA precomp: pre = relu(X@Wf1+bf1) @ M + cvec -------------
#define PC_MT  0
#define PC_A   34816
#define PC_CON (34816 + 2*17408)
#define PC_SMEM (PC_CON + 640*4)

__device__ __forceinline__ void gemm_64(u32 aLd, u32 bLd, float acc[8][4]){
    #pragma unroll
    for (int kk = 0; kk < 8; kk++){
        u32 a0,a1,a2,a3;
        ldsm_x4(aLd + kk*32, a0,a1,a2,a3);
        #pragma unroll
        for (int np = 0; np < 4; np++){
            u32 b0,b1,b2,b3;
            ldsm_x4(bLd + np*(16*PIT*2) + kk*32, b0,b1,b2,b3);
            mma16816(acc[2*np],   a0,a1,a2,a3, b0,b1);
            mma16816(acc[2*np+1], a0,a1,a2,a3, b2,b3);
        }
    }
}

__global__ __launch_bounds__(512, 1) void precomp_hmma(
    const float* __restrict__ pcl, const float* __restrict__ Wf1,
    const float* __restrict__ bf1)
{
    extern __shared__ char smem[];
    u32 sb = smem_u32(smem);
    int tid = threadIdx.x, wg = tid >> 8, w8 = (tid >> 5) & 7, l = tid & 31;
    int wm = w8 & 3, wn = w8 >> 2;

    float4 z4 = make_float4(0.f,0.f,0.f,0.f);
    for (int i = blockIdx.x*512 + tid; i < PTS_TOTAL/4; i += 148*512)
        ((float4*)g_P0)[i] = z4;

    for (int i = tid; i < 34816/16; i += 512)
        ((float4*)smem)[i] = ((const float4*)g_MT)[i];
    float* con = (float*)(smem + PC_CON);
    if (tid < 384) con[tid] = Wf1[tid];
    if (tid >= 384) con[tid] = bf1[tid - 384];
    if (tid < 128) con[512 + tid] = g_cvec[tid];
    __syncthreads();

    const float* sWf = con;
    const float* sb1 = con + 384;
    const float* scv = con + 512;
    float4 f0 = *(const float4*)(sWf + 4*l);
    float4 f1 = *(const float4*)(sWf + 128 + 4*l);
    float4 f2 = *(const float4*)(sWf + 256 + 4*l);
    float4 b1v = *(const float4*)(sb1 + 4*l);

    u32 Abase = sb + PC_A + (u32)(wg*17408);
    u32 aLd = Abase + (u32)(((16*wm + (l & 15))*PIT + 8*(l >> 4)) * 2);
    u32 bLd = sb + PC_MT + (u32)((((wn << 6) + ((l >> 4) << 3) + (l & 7))*PIT
                                  + 8*((l >> 3) & 1)) * 2);
    int barid = 1 + wg;
    int cb = (wn << 6) + 2*(l & 3);
    int rq = l >> 2;
    int r0 = (wm << 4) + rq;

    for (int tile = (blockIdx.x << 1) + wg; tile < BN/64; tile += 296){
        #pragma unroll
        for (int gg = 0; gg < 8; gg++){
            int gr = (tile << 6) + (w8 << 3) + gg;
            const float* xp = pcl + 3*gr;
            float x0 = xp[0], x1 = xp[1], x2 = xp[2];
            float y0 = fmaxf(fmaf(x0,f0.x, fmaf(x1,f1.x, fmaf(x2,f2.x, b1v.x))), 0.f);
            float y1 = fmaxf(fmaf(x0,f0.y, fmaf(x1,f1.y, fmaf(x2,f2.y, b1v.y))), 0.f);
            float y2 = fmaxf(fmaf(x0,f0.z, fmaf(x1,f1.z, fmaf(x2,f2.z, b1v.z))), 0.f);
            float y3 = fmaxf(fmaf(x0,f0.w, fmaf(x1,f1.w, fmaf(x2,f2.w, b1v.w))), 0.f);
            *(uint2*)((char*)smem + (Abase - sb) + ((((w8 << 3) + gg))*PIT + 4*l)*2) =
                make_uint2(packbf(y0,y1), packbf(y2,y3));
        }
        asm volatile("bar.sync %0, 256;" :: "r"(barid) : "memory");

        float acc[8][4];
        #pragma unroll
        for (int nt = 0; nt < 8; nt++){
            acc[nt][0]=0.f; acc[nt][1]=0.f; acc[nt][2]=0.f; acc[nt][3]=0.f;
        }
        gemm_64(aLd, bLd, acc);

        int gr0 = (tile << 6) + r0;
        #pragma unroll
        for (int nt = 0; nt < 8; nt++){
            int c = cb + nt*8;
            *(float2*)(g_pre + (gr0 << 7) + c) =
                make_float2(acc[nt][0] + scv[c], acc[nt][1] + scv[c+1]);
            *(float2*)(g_pre + ((gr0 + 8) << 7) + c) =
                make_float2(acc[nt][2] + scv[c], acc[nt][3] + scv[c+1]);
        }
        asm volatile("bar.sync %0, 256;" :: "r"(barid) : "memory");
    }
}

// ---------------- HMMA step kernel: independent 16-row warp tiles ------------
#define SM_BT 0                       // 2 x 128 x 136 bf16 = 69632
#define SM_A  69632                   // 16 per-warp A0 buffers x 4352 = 69632
#define SM_WX (69632 + 69632)         // 139264: 3 x 128 f32
#define SM_WO (SM_WX+1536)
#define SM_BB (SM_WO+1536)
#define STEP_SMEM (SM_BB+1024)        // 143360

__global__ __launch_bounds__(512, 1) void step_mma_kernel(
    const float* __restrict__ pcl_noisy, const float* __restrict__ W0,
    const float* __restrict__ Wo, const float* __restrict__ bo,
    const float* __restrict__ bb, float s,
    int icur, int inxt, int izero, float* __restrict__ dout)
{
    extern __shared__ char smem[];
    u32 sb = smem_u32(smem);
    int tid = threadIdx.x, w16 = tid >> 5, l = tid & 31;
    int a = l & 3, rq = l >> 2;
    const float* cur = selbuf(icur, pcl_noisy, dout);
    float*       nxt = selbuf(inxt, pcl_noisy, dout);

    if (izero >= 0){
        float4 z4 = make_float4(0.f,0.f,0.f,0.f);
        float* zb = selbuf(izero, pcl_noisy, dout);
        for (int i = blockIdx.x*512 + tid; i < PTS_TOTAL/4; i += 148*512)
            ((float4*)zb)[i] = z4;
    }

    for (int i = tid; i < 69632/16; i += 512)
        ((float4*)(smem+SM_BT))[i] = ((const float4*)g_BT)[i];
    for (int i = tid; i < 384; i += 512) ((float*)(smem+SM_WX))[i] = W0[i];
    if (tid < 128){
        float* wo = (float*)(smem+SM_WO);
        wo[tid] = Wo[tid*3]; wo[128+tid] = Wo[tid*3+1]; wo[256+tid] = Wo[tid*3+2];
    }
    if (tid < 256) ((float*)(smem+SM_BB))[tid] = bb[tid];
    __syncthreads();

    const float* sWx = (const float*)(smem+SM_WX);
    const float* sWo = (const float*)(smem+SM_WO);
    const float* sBB = (const float*)(smem+SM_BB);
    float bo0 = bo[0], bo1 = bo[1], bo2 = bo[2];

    u32 Abase = sb + SM_A + (u32)(w16*4352);
    u32 aLd = Abase + (u32)(((l & 15)*PIT + 8*(l >> 4)) * 2);
    u32 bLd = sb + SM_BT + (u32)(((((l >> 4) << 3) + (l & 7))*PIT
                                  + 8*((l >> 3) & 1)) * 2);
    // layer0 mapping: lane covers group gq=l>>3 (of 4), col block cbk=(l&7)*16
    int gq = l >> 3, cbk = (l & 7) << 4;

    for (int t = w16*148 + blockIdx.x; t < NWT; t += 2368){

        // ---- layer 0: h0 rows 4gq..4gq+3, cols cbk..cbk+15 -> A0 (bf16) ----
        {
            int g = (t << 2) + gq, b = g >> 14, n = g & (NPTS-1);
            const float* cen = pcl_noisy + 3*g;
            float p0 = cen[0], p1 = cen[1], p2 = cen[2];
            float xr[4][3];
            #pragma unroll
            for (int k = 0; k < 4; k++){
                int nb = n + k - 2; nb = nb < 0 ? 0 : (nb > NPTS-1 ? NPTS-1 : nb);
                const float* pc = cur + 3*((b << 14) | nb);
                xr[k][0] = pc[0]-p0; xr[k][1] = pc[1]-p1; xr[k][2] = pc[2]-p2;
            }
            const float* pp = g_pre + (g << 7) + cbk;
            #pragma unroll
            for (int hB = 0; hB < 2; hB++){
                u32 urow[4][4];
                #pragma unroll
                for (int q = 0; q < 2; q++){
                    int c = 8*hB + 4*q;
                    float4 pv = *(const float4*)(pp + c);
                    float4 wa = *(const float4*)(sWx + cbk + c);
                    float4 wb2 = *(const float4*)(sWx + 128 + cbk + c);
                    float4 wc = *(const float4*)(sWx + 256 + cbk + c);
                    #pragma unroll
                    for (int k = 0; k < 4; k++){
                        float y0 = fmaxf(fmaf(xr[k][0],wa.x, fmaf(xr[k][1],wb2.x, fmaf(xr[k][2],wc.x, pv.x))), 0.f);
                        float y1 = fmaxf(fmaf(xr[k][0],wa.y, fmaf(xr[k][1],wb2.y, fmaf(xr[k][2],wc.y, pv.y))), 0.f);
                        float y2 = fmaxf(fmaf(xr[k][0],wa.z, fmaf(xr[k][1],wb2.z, fmaf(xr[k][2],wc.z, pv.z))), 0.f);
                        float y3 = fmaxf(fmaf(xr[k][0],wa.w, fmaf(xr[k][1],wb2.w, fmaf(xr[k][2],wc.w, pv.w))), 0.f);
                        urow[k][2*q]   = packbf(y0, y1);
                        urow[k][2*q+1] = packbf(y2, y3);
                    }
                }
                #pragma unroll
                for (int k = 0; k < 4; k++){
                    u32 adr = Abase + (u32)(((4*gq + k)*PIT + cbk + 8*hB)*2);
                    asm volatile("st.shared.v4.b32 [%0], {%1,%2,%3,%4};"
                        :: "r"(adr), "r"(urow[k][0]), "r"(urow[k][1]),
                           "r"(urow[k][2]), "r"(urow[k][3]));
                }
            }
        }
        __syncwarp();

        // ---- GEMM 1: acc = A0 @ Wb0^T  (A frags kept = h0 bf16) ----
        float acc[16][4];
        u32 af[8][4];
        #pragma unroll
        for (int nt = 0; nt < 16; nt++){
            acc[nt][0]=0.f; acc[nt][1]=0.f; acc[nt][2]=0.f; acc[nt][3]=0.f;
        }
        #pragma unroll
        for (int kk = 0; kk < 8; kk++){
            ldsm_x4(aLd + kk*32, af[kk][0], af[kk][1], af[kk][2], af[kk][3]);
            #pragma unroll
            for (int np = 0; np < 8; np++){
                u32 b0,b1,b2,b3;
                ldsm_x4(bLd + np*(16*PIT*2) + kk*32, b0,b1,b2,b3);
                mma16816(acc[2*np],   af[kk][0],af[kk][1],af[kk][2],af[kk][3], b0,b1);
                mma16816(acc[2*np+1], af[kk][0],af[kk][1],af[kk][2],af[kk][3], b2,b3);
            }
        }

        // ---- epilogue 1 (in regs): af <- bf16(h1), h1 = h0 + relu(acc+bb0)
        #pragma unroll
        for (int kk = 0; kk < 8; kk++){
            int c0 = 16*kk + 2*a, c1 = c0 + 8;
            float2 bba = *(const float2*)(sBB + c0);
            float2 bbb = *(const float2*)(sBB + c1);
            float2 h;
            h = unpackbf(af[kk][0]);
            af[kk][0] = packbf(h.x + fmaxf(acc[2*kk][0] + bba.x, 0.f),
                               h.y + fmaxf(acc[2*kk][1] + bba.y, 0.f));
            h = unpackbf(af[kk][1]);
            af[kk][1] = packbf(h.x + fmaxf(acc[2*kk][2] + bba.x, 0.f),
                               h.y + fmaxf(acc[2*kk][3] + bba.y, 0.f));
            h = unpackbf(af[kk][2]);
            af[kk][2] = packbf(h.x + fmaxf(acc[2*kk+1][0] + bbb.x, 0.f),
                               h.y + fmaxf(acc[2*kk+1][1] + bbb.y, 0.f));
            h = unpackbf(af[kk][3]);
            af[kk][3] = packbf(h.x + fmaxf(acc[2*kk+1][2] + bbb.x, 0.f),
                               h.y + fmaxf(acc[2*kk+1][3] + bbb.y, 0.f));
        }

        // ---- GEMM 2: acc = A1(regs) @ Wb1^T ----
        #pragma unroll
        for (int nt = 0; nt < 16; nt++){
            acc[nt][0]=0.f; acc[nt][1]=0.f; acc[nt][2]=0.f; acc[nt][3]=0.f;
        }
        #pragma unroll
        for (int kk = 0; kk < 8; kk++){
            #pragma unroll
            for (int np = 0; np < 8; np++){
                u32 b0,b1,b2,b3;
                ldsm_x4(bLd + 34816 + np*(16*PIT*2) + kk*32, b0,b1,b2,b3);
                mma16816(acc[2*np],   af[kk][0],af[kk][1],af[kk][2],af[kk][3], b0,b1);
                mma16816(acc[2*np+1], af[kk][0],af[kk][1],af[kk][2],af[kk][3], b2,b3);
            }
        }

        // ---- epilogue 2 (in regs): h2 = h1 + relu(acc+bb1); fused proj ----
        float s0a=0.f,s1a=0.f,s2a=0.f, s0b=0.f,s1b=0.f,s2b=0.f;
        #pragma unroll
        for (int kk = 0; kk < 8; kk++){
            int c0 = 16*kk + 2*a, c1 = c0 + 8;
            float2 bba = *(const float2*)(sBB + 128 + c0);
            float2 bbb = *(const float2*)(sBB + 128 + c1);
            float2 w0a = *(const float2*)(sWo + c0);
            float2 w1a = *(const float2*)(sWo + 128 + c0);
            float2 w2a = *(const float2*)(sWo + 256 + c0);
            float2 w0b = *(const float2*)(sWo + c1);
            float2 w1b = *(const float2*)(sWo + 128 + c1);
            float2 w2b = *(const float2*)(sWo + 256 + c1);
            float2 h; float v0, v1;
            h = unpackbf(af[kk][0]);                      // row rq, cols c0
            v0 = h.x + fmaxf(acc[2*kk][0] + bba.x, 0.f);
            v1 = h.y + fmaxf(acc[2*kk][1] + bba.y, 0.f);
            s0a += v0*w0a.x + v1*w0a.y; s1a += v0*w1a.x + v1*w1a.y; s2a += v0*w2a.x + v1*w2a.y;
            h = unpackbf(af[kk][1]);                      // row rq+8, cols c0
            v0 = h.x + fmaxf(acc[2*kk][2] + bba.x, 0.f);
            v1 = h.y + fmaxf(acc[2*kk][3] + bba.y, 0.f);
            s0b += v0*w0a.x + v1*w0a.y; s1b += v0*w1a.x + v1*w1a.y; s2b += v0*w2a.x + v1*w2a.y;
            h = unpackbf(af[kk][2]);                      // row rq, cols c1
            v0 = h.x + fmaxf(acc[2*kk+1][0] + bbb.x, 0.f);
            v1 = h.y + fmaxf(acc[2*kk+1][1] + bbb.y, 0.f);
            s0a += v0*w0b.x + v1*w0b.y; s1a += v0*w1b.x + v1*w1b.y; s2a += v0*w2b.x + v1*w2b.y;
            h = unpackbf(af[kk][3]);                      // row rq+8, cols c1
            v0 = h.x + fmaxf(acc[2*kk+1][2] + bbb.x, 0.f);
            v1 = h.y + fmaxf(acc[2*kk+1][3] + bbb.y, 0.f);
            s0b += v0*w0b.x + v1*w0b.y; s1b += v0*w1b.x + v1*w1b.y; s2b += v0*w2b.x + v1*w2b.y;
        }
        #pragma unroll
        for (int off = 1; off <= 2; off <<= 1){
            s0a += __shfl_xor_sync(0xffffffffu, s0a, off);
            s1a += __shfl_xor_sync(0xffffffffu, s1a, off);
            s2a += __shfl_xor_sync(0xffffffffu, s2a, off);
            s0b += __shfl_xor_sync(0xffffffffu, s0b, off);
            s1b += __shfl_xor_sync(0xffffffffu, s1b, off);
            s2b += __shfl_xor_sync(0xffffffffu, s2b, off);
        }
        if (a == 0){
            #pragma unroll
            for (int hh = 0; hh < 2; hh++){
                int row = rq + (hh << 3);                 // 0..15
                int g = (t << 2) + (row >> 2);
                int b = g >> 14, n = g & (NPTS-1), k = row & 3;
                int nb = n + k - 2; nb = nb < 0 ? 0 : (nb > NPTS-1 ? NPTS-1 : nb);
                int didx = (b << 14) | nb;
                float* dst = nxt + 3*didx;
                float u0 = hh ? s0b : s0a, u1 = hh ? s1b : s1a, u2 = hh ? s2b : s2a;
                float sd0 = 0.f, sd1 = 0.f, sd2 = 0.f;
                if (k == 2){
                    const float* cp = cur + 3*didx;
                    sd0 = cp[0]; sd1 = cp[1]; sd2 = cp[2];
                }
                atomicAdd(dst + 0, s*(u0 + bo0) + sd0);
                atomicAdd(dst + 1, s*(u1 + bo1) + sd1);
                atomicAdd(dst + 2, s*(u2 + bo2) + sd2);
            }
        }
        __syncwarp();   // all lanes done reading A0 before next tile's STS
    }
}

// ---------------------------------------------------------------------------
extern "C" void kernel_launch(void* const* d_in, const int* in_sizes, int n_in,
                              void* d_out, int out_size)
{
    const float* pcl = (const float*)d_in[0];
    const float* Wf1 = (const float*)d_in[1];
    const float* bf1 = (const float*)d_in[2];
    const float* Wf2 = (const float*)d_in[3];
    const float* bf2 = (const float*)d_in[4];
    const float* W0  = (const float*)d_in[5];
    const float* b0  = (const float*)d_in[6];
    const float* Wb  = (const float*)d_in[7];
    const float* bb  = (const float*)d_in[8];
    const float* Wo  = (const float*)d_in[9];
    const float* bo  = (const float*)d_in[10];
    float* dout = (float*)d_out;

    cudaFuncSetAttribute(precomp_hmma, cudaFuncAttributeMaxDynamicSharedMemorySize, PC_SMEM);
    cudaFuncSetAttribute(step_mma_kernel, cudaFuncAttributeMaxDynamicSharedMemorySize, STEP_SMEM);

    prep_fused<<<385, 128>>>(Wf2, W0, b0, bf2, Wb);
    precomp_hmma<<<148, 512, PC_SMEM>>>(pcl, Wf1, bf1);   // also zeroes P0

    float s = 0.2f;
    step_mma_kernel<<<148, 512, STEP_SMEM>>>(pcl, W0, Wo, bo, bb, s, 3, 0, 1, dout);
    s *= 0.95f;
    step_mma_kernel<<<148, 512, STEP_SMEM>>>(pcl, W0, Wo, bo, bb, s, 0, 1, 2, dout);
    s *= 0.95f;
    step_mma_kernel<<<148, 512, STEP_SMEM>>>(pcl, W0, Wo, bo, bb, s, 1, 2, 4, dout);
    s *= 0.95f;
    step_mma_kernel<<<148, 512, STEP_SMEM>>>(pcl, W0, Wo, bo, bb, s, 2, 4, -1, dout);
}

// round 14
// speedup vs baseline: 6.9642x; 1.0695x over previous
#include <cuda_runtime.h>
#include <cuda_bf16.h>

#define BATCH 2
#define NPTS  16384
#define FDIM  128
#define BN    (BATCH*NPTS)           // 32768 groups
#define PTS_TOTAL (BATCH*NPTS*3)     // 98304 floats
#define PIT   136                    // bf16 row pitch (272B: conflict-free ldmatrix)
#define NWT   8192                   // 131072 rows / 16-row warp tiles
typedef unsigned int u32;

// ---------------- low-level helpers -----------------------------------------
__device__ __forceinline__ u32 smem_u32(const void* p){
    u32 a; asm("{ .reg .u64 t; cvta.to.shared.u64 t, %1; cvt.u32.u64 %0, t; }"
               : "=r"(a) : "l"(p));
    return a;
}
__device__ __forceinline__ void ldsm_x4(u32 a, u32& r0, u32& r1, u32& r2, u32& r3){
    asm volatile("ldmatrix.sync.aligned.m8n8.x4.shared.b16 {%0,%1,%2,%3}, [%4];"
                 : "=r"(r0),"=r"(r1),"=r"(r2),"=r"(r3) : "r"(a));
}
__device__ __forceinline__ void mma16816(float* c, u32 a0, u32 a1, u32 a2, u32 a3,
                                         u32 b0, u32 b1){
    asm volatile("mma.sync.aligned.m16n8k16.row.col.f32.bf16.bf16.f32 "
                 "{%0,%1,%2,%3}, {%4,%5,%6,%7}, {%8,%9}, {%0,%1,%2,%3};"
                 : "+f"(c[0]),"+f"(c[1]),"+f"(c[2]),"+f"(c[3])
                 : "r"(a0),"r"(a1),"r"(a2),"r"(a3),"r"(b0),"r"(b1));
}
__device__ __forceinline__ u32 packbf(float x, float y){
    __nv_bfloat162 p = __floats2bfloat162_rn(x, y);
    return *(u32*)&p;
}
__device__ __forceinline__ float2 unpackbf(u32 v){
    return __bfloat1622float2(*(__nv_bfloat162*)&v);
}

// ---------------- scratch ----------------------------------------------------
__device__ float  g_pre[BN*FDIM];     // feat@W0f + b0 (precomputed, 16MB)
__device__ float  g_cvec[FDIM];
__device__ float  g_P0[PTS_TOTAL];
__device__ float  g_P1[PTS_TOTAL];
__device__ float  g_P2[PTS_TOTAL];
__device__ __nv_bfloat16 g_BT[2*FDIM*PIT];   // WbT bf16, pitch 136
__device__ __nv_bfloat16 g_MT[FDIM*PIT];     // (Wf2@W0f)^T bf16, pitch 136

__device__ __forceinline__ float* selbuf(int s_, const float* pcl, float* dout){
    if (s_ == 0) return g_P0;
    if (s_ == 1) return g_P1;
    if (s_ == 2) return g_P2;
    if (s_ == 4) return dout;
    return (float*)pcl;
}

// ---------------- fused prep: M^T, cvec, WbT ---------------------------------
__global__ void prep_fused(const float* __restrict__ Wf2, const float* __restrict__ W0,
                           const float* __restrict__ b0, const float* __restrict__ bf2,
                           const float* __restrict__ Wb){
    int bid = blockIdx.x, j = threadIdx.x;
    if (bid < 128){
        int i = bid;
        float a = 0.f;
        for (int c = 0; c < FDIM; c++) a = fmaf(Wf2[i*FDIM+c], W0[(3+c)*FDIM + j], a);
        g_MT[j*PIT + i] = __float2bfloat16(a);
    } else if (bid == 128){
        float a = b0[j];
        for (int c = 0; c < FDIM; c++) a = fmaf(bf2[c], W0[(3+c)*FDIM + j], a);
        g_cvec[j] = a;
    } else {
        int b2 = bid - 129;
        int lay = b2 >> 7, n = b2 & 127, k = j;
        g_BT[(lay*FDIM + n)*PIT + k] = __float2bfloat16(Wb[(lay*FDIM + k)*FDIM + n]);
    }
}

// ---------------- HMMA precomp: pre = relu(X@Wf1+bf1) @ M + cvec -------------
#define PC_MT  0
#define PC_A   34816
#define PC_CON (34816 + 2*17408)
#define PC_SMEM (PC_CON + 640*4)

__device__ __forceinline__ void gemm_64(u32 aLd, u32 bLd, float acc[8][4]){
    #pragma unroll
    for (int kk = 0; kk < 8; kk++){
        u32 a0,a1,a2,a3;
        ldsm_x4(aLd + kk*32, a0,a1,a2,a3);
        #pragma unroll
        for (int np = 0; np < 4; np++){
            u32 b0,b1,b2,b3;
            ldsm_x4(bLd + np*(16*PIT*2) + kk*32, b0,b1,b2,b3);
            mma16816(acc[2*np],   a0,a1,a2,a3, b0,b1);
            mma16816(acc[2*np+1], a0,a1,a2,a3, b2,b3);
        }
    }
}

__global__ __launch_bounds__(512, 1) void precomp_hmma(
    const float* __restrict__ pcl, const float* __restrict__ Wf1,
    const float* __restrict__ bf1)
{
    extern __shared__ char smem[];
    u32 sb = smem_u32(smem);
    int tid = threadIdx.x, wg = tid >> 8, w8 = (tid >> 5) & 7, l = tid & 31;
    int wm = w8 & 3, wn = w8 >> 2;

    float4 z4 = make_float4(0.f,0.f,0.f,0.f);
    for (int i = blockIdx.x*512 + tid; i < PTS_TOTAL/4; i += 148*512)
        ((float4*)g_P0)[i] = z4;

    for (int i = tid; i < 34816/16; i += 512)
        ((float4*)smem)[i] = ((const float4*)g_MT)[i];
    float* con = (float*)(smem + PC_CON);
    if (tid < 384) con[tid] = Wf1[tid];
    if (tid >= 384) con[tid] = bf1[tid - 384];
    if (tid < 128) con[512 + tid] = g_cvec[tid];
    __syncthreads();

    const float* sWf = con;
    const float* sb1 = con + 384;
    const float* scv = con + 512;
    float4 f0 = *(const float4*)(sWf + 4*l);
    float4 f1 = *(const float4*)(sWf + 128 + 4*l);
    float4 f2 = *(const float4*)(sWf + 256 + 4*l);
    float4 b1v = *(const float4*)(sb1 + 4*l);

    u32 Abase = sb + PC_A + (u32)(wg*17408);
    u32 aLd = Abase + (u32)(((16*wm + (l & 15))*PIT + 8*(l >> 4)) * 2);
    u32 bLd = sb + PC_MT + (u32)((((wn << 6) + ((l >> 4) << 3) + (l & 7))*PIT
                                  + 8*((l >> 3) & 1)) * 2);
    int barid = 1 + wg;
    int cb = (wn << 6) + 2*(l & 3);
    int rq = l >> 2;
    int r0 = (wm << 4) + rq;

    for (int tile = (blockIdx.x << 1) + wg; tile < BN/64; tile += 296){
        #pragma unroll
        for (int gg = 0; gg < 8; gg++){
            int gr = (tile << 6) + (w8 << 3) + gg;
            const float* xp = pcl + 3*gr;
            float x0 = xp[0], x1 = xp[1], x2 = xp[2];
            float y0 = fmaxf(fmaf(x0,f0.x, fmaf(x1,f1.x, fmaf(x2,f2.x, b1v.x))), 0.f);
            float y1 = fmaxf(fmaf(x0,f0.y, fmaf(x1,f1.y, fmaf(x2,f2.y, b1v.y))), 0.f);
            float y2 = fmaxf(fmaf(x0,f0.z, fmaf(x1,f1.z, fmaf(x2,f2.z, b1v.z))), 0.f);
            float y3 = fmaxf(fmaf(x0,f0.w, fmaf(x1,f1.w, fmaf(x2,f2.w, b1v.w))), 0.f);
            *(uint2*)((char*)smem + (Abase - sb) + ((((w8 << 3) + gg))*PIT + 4*l)*2) =
                make_uint2(packbf(y0,y1), packbf(y2,y3));
        }
        asm volatile("bar.sync %0, 256;" :: "r"(barid) : "memory");

        float acc[8][4];
        #pragma unroll
        for (int nt = 0; nt < 8; nt++){
            acc[nt][0]=0.f; acc[nt][1]=0.f; acc[nt][2]=0.f; acc[nt][3]=0.f;
        }
        gemm_64(aLd, bLd, acc);

        int gr0 = (tile << 6) + r0;
        #pragma unroll
        for (int nt = 0; nt < 8; nt++){
            int c = cb + nt*8;
            *(float2*)(g_pre + (gr0 << 7) + c) =
                make_float2(acc[nt][0] + scv[c], acc[nt][1] + scv[c+1]);
            *(float2*)(g_pre + ((gr0 + 8) << 7) + c) =
                make_float2(acc[nt][2] + scv[c], acc[nt][3] + scv[c+1]);
        }
        asm volatile("bar.sync %0, 256;" :: "r"(barid) : "memory");
    }
}

// ---------------- HMMA step kernel: independent 16-row warp tiles ------------
// n-blocked GEMMs: h0/h1 fragments resident (32+32 regs), accumulator slab
// only 16 regs live -> no spills at the 128-reg/thread HW cap.
#define SM_BT 0                       // 2 x 128 x 136 bf16 = 69632
#define SM_A  69632                   // 16 per-warp A0 buffers x 4352 = 69632
#define SM_WX (69632 + 69632)         // 139264: 3 x 128 f32
#define SM_WO (SM_WX+1536)
#define SM_BB (SM_WO+1536)
#define STEP_SMEM (SM_BB+1024)        // 143360

__global__ __launch_bounds__(512, 1) void step_mma_kernel(
    const float* __restrict__ pcl_noisy, const float* __restrict__ W0,
    const float* __restrict__ Wo, const float* __restrict__ bo,
    const float* __restrict__ bb, float s,
    int icur, int inxt, int izero, float* __restrict__ dout)
{
    extern __shared__ char smem[];
    u32 sb = smem_u32(smem);
    int tid = threadIdx.x, w16 = tid >> 5, l = tid & 31;
    int a = l & 3, rq = l >> 2;
    const float* cur = selbuf(icur, pcl_noisy, dout);
    float*       nxt = selbuf(inxt, pcl_noisy, dout);

    if (izero >= 0){
        float4 z4 = make_float4(0.f,0.f,0.f,0.f);
        float* zb = selbuf(izero, pcl_noisy, dout);
        for (int i = blockIdx.x*512 + tid; i < PTS_TOTAL/4; i += 148*512)
            ((float4*)zb)[i] = z4;
    }

    for (int i = tid; i < 69632/16; i += 512)
        ((float4*)(smem+SM_BT))[i] = ((const float4*)g_BT)[i];
    for (int i = tid; i < 384; i += 512) ((float*)(smem+SM_WX))[i] = W0[i];
    if (tid < 128){
        float* wo = (float*)(smem+SM_WO);
        wo[tid] = Wo[tid*3]; wo[128+tid] = Wo[tid*3+1]; wo[256+tid] = Wo[tid*3+2];
    }
    if (tid < 256) ((float*)(smem+SM_BB))[tid] = bb[tid];
    __syncthreads();

    const float* sWx = (const float*)(smem+SM_WX);
    const float* sWo = (const float*)(smem+SM_WO);
    const float* sBB = (const float*)(smem+SM_BB);
    float bo0 = bo[0], bo1 = bo[1], bo2 = bo[2];

    u32 Abase = sb + SM_A + (u32)(w16*4352);
    u32 aLd = Abase + (u32)(((l & 15)*PIT + 8*(l >> 4)) * 2);
    u32 bLd = sb + SM_BT + (u32)(((((l >> 4) << 3) + (l & 7))*PIT
                                  + 8*((l >> 3) & 1)) * 2);
    // layer0 mapping: lane covers group gq=l>>3 (of 4), col block cbk=(l&7)*16
    int gq = l >> 3, cbk = (l & 7) << 4;

    for (int t = w16*148 + blockIdx.x; t < NWT; t += 2368){

        // ---- layer 0: h0 rows 4gq..4gq+3, cols cbk..cbk+15 -> A0 (bf16) ----
        {
            int g = (t << 2) + gq, b = g >> 14, n = g & (NPTS-1);
            const float* cen = pcl_noisy + 3*g;
            float p0 = cen[0], p1 = cen[1], p2 = cen[2];
            float xr[4][3];
            #pragma unroll
            for (int k = 0; k < 4; k++){
                int nb = n + k - 2; nb = nb < 0 ? 0 : (nb > NPTS-1 ? NPTS-1 : nb);
                const float* pc = cur + 3*((b << 14) | nb);
                xr[k][0] = pc[0]-p0; xr[k][1] = pc[1]-p1; xr[k][2] = pc[2]-p2;
            }
            const float* pp = g_pre + (g << 7) + cbk;
            #pragma unroll
            for (int hB = 0; hB < 2; hB++){
                u32 urow[4][4];
                #pragma unroll
                for (int q = 0; q < 2; q++){
                    int c = 8*hB + 4*q;
                    float4 pv = *(const float4*)(pp + c);
                    float4 wa = *(const float4*)(sWx + cbk + c);
                    float4 wb2 = *(const float4*)(sWx + 128 + cbk + c);
                    float4 wc = *(const float4*)(sWx + 256 + cbk + c);
                    #pragma unroll
                    for (int k = 0; k < 4; k++){
                        float y0 = fmaxf(fmaf(xr[k][0],wa.x, fmaf(xr[k][1],wb2.x, fmaf(xr[k][2],wc.x, pv.x))), 0.f);
                        float y1 = fmaxf(fmaf(xr[k][0],wa.y, fmaf(xr[k][1],wb2.y, fmaf(xr[k][2],wc.y, pv.y))), 0.f);
                        float y2 = fmaxf(fmaf(xr[k][0],wa.z, fmaf(xr[k][1],wb2.z, fmaf(xr[k][2],wc.z, pv.z))), 0.f);
                        float y3 = fmaxf(fmaf(xr[k][0],wa.w, fmaf(xr[k][1],wb2.w, fmaf(xr[k][2],wc.w, pv.w))), 0.f);
                        urow[k][2*q]   = packbf(y0, y1);
                        urow[k][2*q+1] = packbf(y2, y3);
                    }
                }
                #pragma unroll
                for (int k = 0; k < 4; k++){
                    u32 adr = Abase + (u32)(((4*gq + k)*PIT + cbk + 8*hB)*2);
                    asm volatile("st.shared.v4.b32 [%0], {%1,%2,%3,%4};"
                        :: "r"(adr), "r"(urow[k][0]), "r"(urow[k][1]),
                           "r"(urow[k][2]), "r"(urow[k][3]));
                }
            }
        }
        __syncwarp();

        // ---- load h0 fragments (resident through GEMM1) ----
        u32 h0[8][4];
        #pragma unroll
        for (int kk = 0; kk < 8; kk++)
            ldsm_x4(aLd + kk*32, h0[kk][0], h0[kk][1], h0[kk][2], h0[kk][3]);

        // ---- GEMM1 + epilogue1, n-blocked (np pairs): h1 = h0 + relu(.+bb0)
        u32 h1[8][4];
        #pragma unroll
        for (int npp = 0; npp < 4; npp++){
            float acc[4][4];
            #pragma unroll
            for (int j = 0; j < 4; j++){
                acc[j][0]=0.f; acc[j][1]=0.f; acc[j][2]=0.f; acc[j][3]=0.f;
            }
            #pragma unroll
            for (int kk = 0; kk < 8; kk++){
                u32 b0,b1,b2,b3, c0,c1,c2,c3;
                ldsm_x4(bLd + (2*npp)*(16*PIT*2) + kk*32, b0,b1,b2,b3);
                ldsm_x4(bLd + (2*npp+1)*(16*PIT*2) + kk*32, c0,c1,c2,c3);
                mma16816(acc[0], h0[kk][0],h0[kk][1],h0[kk][2],h0[kk][3], b0,b1);
                mma16816(acc[1], h0[kk][0],h0[kk][1],h0[kk][2],h0[kk][3], b2,b3);
                mma16816(acc[2], h0[kk][0],h0[kk][1],h0[kk][2],h0[kk][3], c0,c1);
                mma16816(acc[3], h0[kk][0],h0[kk][1],h0[kk][2],h0[kk][3], c2,c3);
            }
            #pragma unroll
            for (int j = 0; j < 2; j++){
                int np = 2*npp + j;
                int c0i = 16*np + 2*a, c1i = c0i + 8;
                float2 bba = *(const float2*)(sBB + c0i);
                float2 bbb = *(const float2*)(sBB + c1i);
                float2 h;
                h = unpackbf(h0[np][0]);
                h1[np][0] = packbf(h.x + fmaxf(acc[2*j][0] + bba.x, 0.f),
                                   h.y + fmaxf(acc[2*j][1] + bba.y, 0.f));
                h = unpackbf(h0[np][1]);
                h1[np][1] = packbf(h.x + fmaxf(acc[2*j][2] + bba.x, 0.f),
                                   h.y + fmaxf(acc[2*j][3] + bba.y, 0.f));
                h = unpackbf(h0[np][2]);
                h1[np][2] = packbf(h.x + fmaxf(acc[2*j+1][0] + bbb.x, 0.f),
                                   h.y + fmaxf(acc[2*j+1][1] + bbb.y, 0.f));
                h = unpackbf(h0[np][3]);
                h1[np][3] = packbf(h.x + fmaxf(acc[2*j+1][2] + bbb.x, 0.f),
                                   h.y + fmaxf(acc[2*j+1][3] + bbb.y, 0.f));
            }
        }

        // ---- GEMM2 + epilogue2, n-blocked; fused 128->3 projection ----
        float s0a=0.f,s1a=0.f,s2a=0.f, s0b=0.f,s1b=0.f,s2b=0.f;
        #pragma unroll
        for (int npp = 0; npp < 4; npp++){
            float acc[4][4];
            #pragma unroll
            for (int j = 0; j < 4; j++){
                acc[j][0]=0.f; acc[j][1]=0.f; acc[j][2]=0.f; acc[j][3]=0.f;
            }
            #pragma unroll
            for (int kk = 0; kk < 8; kk++){
                u32 b0,b1,b2,b3, c0,c1,c2,c3;
                ldsm_x4(bLd + 34816 + (2*npp)*(16*PIT*2) + kk*32, b0,b1,b2,b3);
                ldsm_x4(bLd + 34816 + (2*npp+1)*(16*PIT*2) + kk*32, c0,c1,c2,c3);
                mma16816(acc[0], h1[kk][0],h1[kk][1],h1[kk][2],h1[kk][3], b0,b1);
                mma16816(acc[1], h1[kk][0],h1[kk][1],h1[kk][2],h1[kk][3], b2,b3);
                mma16816(acc[2], h1[kk][0],h1[kk][1],h1[kk][2],h1[kk][3], c0,c1);
                mma16816(acc[3], h1[kk][0],h1[kk][1],h1[kk][2],h1[kk][3], c2,c3);
            }
            #pragma unroll
            for (int j = 0; j < 2; j++){
                int np = 2*npp + j;
                int c0i = 16*np + 2*a, c1i = c0i + 8;
                float2 bba = *(const float2*)(sBB + 128 + c0i);
                float2 bbb = *(const float2*)(sBB + 128 + c1i);
                float2 w0a = *(const float2*)(sWo + c0i);
                float2 w1a = *(const float2*)(sWo + 128 + c0i);
                float2 w2a = *(const float2*)(sWo + 256 + c0i);
                float2 w0b = *(const float2*)(sWo + c1i);
                float2 w1b = *(const float2*)(sWo + 128 + c1i);
                float2 w2b = *(const float2*)(sWo + 256 + c1i);
                float2 h; float v0, v1;
                h = unpackbf(h1[np][0]);                  // row rq, cols c0i
                v0 = h.x + fmaxf(acc[2*j][0] + bba.x, 0.f);
                v1 = h.y + fmaxf(acc[2*j][1] + bba.y, 0.f);
                s0a += v0*w0a.x + v1*w0a.y; s1a += v0*w1a.x + v1*w1a.y; s2a += v0*w2a.x + v1*w2a.y;
                h = unpackbf(h1[np][1]);                  // row rq+8, cols c0i
                v0 = h.x + fmaxf(acc[2*j][2] + bba.x, 0.f);
                v1 = h.y + fmaxf(acc[2*j][3] + bba.y, 0.f);
                s0b += v0*w0a.x + v1*w0a.y; s1b += v0*w1a.x + v1*w1a.y; s2b += v0*w2a.x + v1*w2a.y;
                h = unpackbf(h1[np][2]);                  // row rq, cols c1i
                v0 = h.x + fmaxf(acc[2*j+1][0] + bbb.x, 0.f);
                v1 = h.y + fmaxf(acc[2*j+1][1] + bbb.y, 0.f);
                s0a += v0*w0b.x + v1*w0b.y; s1a += v0*w1b.x + v1*w1b.y; s2a += v0*w2b.x + v1*w2b.y;
                h = unpackbf(h1[np][3]);                  // row rq+8, cols c1i
                v0 = h.x + fmaxf(acc[2*j+1][2] + bbb.x, 0.f);
                v1 = h.y + fmaxf(acc[2*j+1][3] + bbb.y, 0.f);
                s0b += v0*w0b.x + v1*w0b.y; s1b += v0*w1b.x + v1*w1b.y; s2b += v0*w2b.x + v1*w2b.y;
            }
        }
        #pragma unroll
        for (int off = 1; off <= 2; off <<= 1){
            s0a += __shfl_xor_sync(0xffffffffu, s0a, off);
            s1a += __shfl_xor_sync(0xffffffffu, s1a, off);
            s2a += __shfl_xor_sync(0xffffffffu, s2a, off);
            s0b += __shfl_xor_sync(0xffffffffu, s0b, off);
            s1b += __shfl_xor_sync(0xffffffffu, s1b, off);
            s2b += __shfl_xor_sync(0xffffffffu, s2b, off);
        }
        if (a == 0){
            #pragma unroll
            for (int hh = 0; hh < 2; hh++){
                int row = rq + (hh << 3);                 // 0..15
                int g = (t << 2) + (row >> 2);
                int b = g >> 14, n = g & (NPTS-1), k = row & 3;
                int nb = n + k - 2; nb = nb < 0 ? 0 : (nb > NPTS-1 ? NPTS-1 : nb);
                int didx = (b << 14) | nb;
                float* dst = nxt + 3*didx;
                float u0 = hh ? s0b : s0a, u1 = hh ? s1b : s1a, u2 = hh ? s2b : s2a;
                float sd0 = 0.f, sd1 = 0.f, sd2 = 0.f;
                if (k == 2){
                    const float* cp = cur + 3*didx;
                    sd0 = cp[0]; sd1 = cp[1]; sd2 = cp[2];
                }
                atomicAdd(dst + 0, s*(u0 + bo0) + sd0);
                atomicAdd(dst + 1, s*(u1 + bo1) + sd1);
                atomicAdd(dst + 2, s*(u2 + bo2) + sd2);
            }
        }
        __syncwarp();   // all lanes done reading A0 before next tile's STS
    }
}

// ---------------------------------------------------------------------------
extern "C" void kernel_launch(void* const* d_in, const int* in_sizes, int n_in,
                              void* d_out, int out_size)
{
    const float* pcl = (const float*)d_in[0];
    const float* Wf1 = (const float*)d_in[1];
    const float* bf1 = (const float*)d_in[2];
    const float* Wf2 = (const float*)d_in[3];
    const float* bf2 = (const float*)d_in[4];
    const float* W0  = (const float*)d_in[5];
    const float* b0  = (const float*)d_in[6];
    const float* Wb  = (const float*)d_in[7];
    const float* bb  = (const float*)d_in[8];
    const float* Wo  = (const float*)d_in[9];
    const float* bo  = (const float*)d_in[10];
    float* dout = (float*)d_out;

    cudaFuncSetAttribute(precomp_hmma, cudaFuncAttributeMaxDynamicSharedMemorySize, PC_SMEM);
    cudaFuncSetAttribute(step_mma_kernel, cudaFuncAttributeMaxDynamicSharedMemorySize, STEP_SMEM);

    prep_fused<<<385, 128>>>(Wf2, W0, b0, bf2, Wb);
    precomp_hmma<<<148, 512, PC_SMEM>>>(pcl, Wf1, bf1);   // also zeroes P0

    float s = 0.2f;
    step_mma_kernel<<<148, 512, STEP_SMEM>>>(pcl, W0, Wo, bo, bb, s, 3, 0, 1, dout);
    s *= 0.95f;
    step_mma_kernel<<<148, 512, STEP_SMEM>>>(pcl, W0, Wo, bo, bb, s, 0, 1, 2, dout);
    s *= 0.95f;
    step_mma_kernel<<<148, 512, STEP_SMEM>>>(pcl, W0, Wo, bo, bb, s, 1, 2, 4, dout);
    s *= 0.95f;
    step_mma_kernel<<<148, 512, STEP_SMEM>>>(pcl, W0, Wo, bo, bb, s, 2, 4, -1, dout);
}